// round 14
// baseline (speedup 1.0000x reference)
#include <cuda_runtime.h>
#include <math.h>

#define BB 128
#define CC 16
#define HH 9
#define TT 2048
#define LL 9

__device__ float g_buf0[BB*CC*HH*TT];
__device__ float g_buf1[BB*CC*HH*(TT/2)];
__device__ float g_rowsum[2*BB*2*CC*HH];
__device__ float g_scale[BB];

// accurate fast tanh: 2 MUFU + few ALU, abs err ~1e-6
__device__ __forceinline__ float tanh_acc(float x){
    float ax = fabsf(x);
    float e;
    asm("ex2.approx.f32 %0, %1;" : "=f"(e) : "f"(-2.8853900817779268f * ax));
    float r;
    asm("rcp.approx.f32 %0, %1;" : "=f"(r) : "f"(1.0f + e));
    float t = (1.0f - e) * r;
    return copysignf(t, x);
}
__device__ __forceinline__ float prelu_f(float u, float a){ return u >= 0.f ? u : a*u; }

// ---- packed f32x2 helpers (sm_100+; ptxas never auto-fuses FFMA2) ----
typedef unsigned long long u64p;
__device__ __forceinline__ u64p pack2(float lo, float hi){
    u64p r; asm("mov.b64 %0, {%1,%2};" : "=l"(r) : "f"(lo), "f"(hi)); return r;
}
__device__ __forceinline__ void unpack2(u64p v, float& lo, float& hi){
    asm("mov.b64 {%0,%1}, %2;" : "=f"(lo), "=f"(hi) : "l"(v));
}
__device__ __forceinline__ u64p fma2(u64p a, u64p b, u64p c){
    u64p d; asm("fma.rn.f32x2 %0, %1, %2, %3;" : "=l"(d) : "l"(a), "l"(b), "l"(c)); return d;
}

// =============== front: conv33 + BN/PReLU + conv3 + BN/PReLU (tiled 1024) ====
// co-split: each work item covers 8 of 16 output channels -> acc[8][4] (no spill)
__global__ __launch_bounds__(256) void front_kernel(const float* __restrict__ x,
    const float* __restrict__ Wc1, const float* __restrict__ bc1,
    const float* __restrict__ g1, const float* __restrict__ b1, const float* __restrict__ a1p,
    const float* __restrict__ Wc2, const float* __restrict__ bc2,
    const float* __restrict__ g2, const float* __restrict__ b2, const float* __restrict__ a2p)
{
    extern __shared__ float sm[];
    float* wc1s = sm;          // [c][36] zero-padded
    float* w2k  = sm + 576;    // [ci][k][co]
    float* prm  = sm + 1344;   // 6x16
    float* xr   = sm + 1440;   // 1072
    float* ys   = sm + 2512;   // 16*1032

    const int tid = threadIdx.x;
    const int ti = blockIdx.x & 1;
    const int bh = blockIdx.x >> 1;
    const int b = bh / HH, h = bh % HH;
    const int lo = ti * 1024;

    for (int i = tid; i < 576; i += 256) { int c = i/36, k = i%36; wc1s[i] = (k < 33) ? Wc1[c*33+k] : 0.f; }
    for (int i = tid; i < 768; i += 256) { int co = i & 15, k = (i >> 4) % 3, ci = i / 48; w2k[i] = Wc2[(co*16+ci)*3+k]; }
    if (tid < 16) {
        prm[tid]    = bc1[tid]; prm[16+tid] = g1[tid]; prm[32+tid] = b1[tid];
        prm[48+tid] = bc2[tid]; prm[64+tid] = g2[tid]; prm[80+tid] = b2[tid];
    }
    for (int m = tid; m < 1072; m += 256) {
        int g = lo - 17 + m;
        xr[m] = (m < 1058 && g >= 0 && g < TT) ? x[(b*HH+h)*TT + g] : 0.f;
    }
    __syncthreads();
    const float a1 = a1p[0], a2 = a2p[0];
    const float4* x4  = (const float4*)xr;
    const float4* w14 = (const float4*)wc1s;

    // conv1 over ys-relative positions [0,1026): global j = lo-1 + rel
    for (int it = tid; it < 514; it += 256) {
        int q4 = it >> 1;
        int cb = (it & 1) * 8;
        float acc[8][4];
        #pragma unroll
        for (int c = 0; c < 8; c++) { acc[c][0]=0.f; acc[c][1]=0.f; acc[c][2]=0.f; acc[c][3]=0.f; }
        float4 xq = x4[q4];
        #pragma unroll
        for (int kb = 0; kb < 9; kb++) {
            float4 xn = x4[q4 + kb + 1];
            #pragma unroll
            for (int c = 0; c < 8; c++) {
                float4 w = w14[(cb + c)*9 + kb];
                acc[c][0]=fmaf(w.x,xq.x,fmaf(w.y,xq.y,fmaf(w.z,xq.z,fmaf(w.w,xq.w,acc[c][0]))));
                acc[c][1]=fmaf(w.x,xq.y,fmaf(w.y,xq.z,fmaf(w.z,xq.w,fmaf(w.w,xn.x,acc[c][1]))));
                acc[c][2]=fmaf(w.x,xq.z,fmaf(w.y,xq.w,fmaf(w.z,xn.x,fmaf(w.w,xn.y,acc[c][2]))));
                acc[c][3]=fmaf(w.x,xq.w,fmaf(w.y,xn.x,fmaf(w.z,xn.y,fmaf(w.w,xn.z,acc[c][3]))));
            }
            xq = xn;
        }
        #pragma unroll
        for (int c = 0; c < 8; c++) {
            int cc = cb + c;
            float r[4];
            #pragma unroll
            for (int p = 0; p < 4; p++) {
                int jg = lo - 1 + q4*4 + p;
                float u = (acc[c][p] + prm[cc]) * prm[16+cc] + prm[32+cc];
                r[p] = (jg >= 0 && jg < TT) ? prelu_f(u, a1) : 0.f;   // zero pad for conv2
            }
            if (q4 < 256) {
                float4 v; v.x=r[0]; v.y=r[1]; v.z=r[2]; v.w=r[3];
                *(float4*)(ys + cc*1032 + q4*4) = v;
            } else {
                ys[cc*1032 + 1024] = r[0]; ys[cc*1032 + 1025] = r[1];
            }
        }
    }
    __syncthreads();

    // conv2 (1x3) over j in [lo, hi)
    for (int it = tid; it < 512; it += 256) {
        int id = it >> 1;
        int cb = (it & 1) * 8;
        int j0 = lo + id*4;
        float acc[8][4];
        #pragma unroll
        for (int c = 0; c < 8; c++) { acc[c][0]=0.f; acc[c][1]=0.f; acc[c][2]=0.f; acc[c][3]=0.f; }
        #pragma unroll
        for (int ci = 0; ci < 16; ci++) {
            const float* yrow = ys + ci*1032 + id*4;
            float4 v03 = *(const float4*)yrow;
            float win[6]; win[0]=v03.x; win[1]=v03.y; win[2]=v03.z; win[3]=v03.w;
            win[4]=yrow[4]; win[5]=yrow[5];
            #pragma unroll
            for (int k = 0; k < 3; k++) {
                const float4* w4p = (const float4*)(w2k + ci*48 + k*16 + cb);
                #pragma unroll
                for (int q = 0; q < 2; q++) {
                    float4 w = w4p[q];
                    #pragma unroll
                    for (int p = 0; p < 4; p++) {
                        float v = win[p+k];
                        acc[q*4+0][p]=fmaf(w.x,v,acc[q*4+0][p]);
                        acc[q*4+1][p]=fmaf(w.y,v,acc[q*4+1][p]);
                        acc[q*4+2][p]=fmaf(w.z,v,acc[q*4+2][p]);
                        acc[q*4+3][p]=fmaf(w.w,v,acc[q*4+3][p]);
                    }
                }
            }
        }
        #pragma unroll
        for (int c = 0; c < 8; c++) {
            int co = cb + c;
            float4 r; float rp[4];
            #pragma unroll
            for (int p = 0; p < 4; p++) {
                float u = (acc[c][p] + prm[48+co]) * prm[64+co] + prm[80+co];
                rp[p] = prelu_f(u, a2);
            }
            r.x=rp[0]; r.y=rp[1]; r.z=rp[2]; r.w=rp[3];
            *(float4*)(g_buf0 + (((size_t)b*16 + co)*9 + h)*TT + j0) = r;
        }
    }
}

// ==== lifting level (levels 0..3, tiled, 2-pos chunks, packed f32x2 FMA) ====
__global__ void lift_kernel(
    const float* __restrict__ WU1, const float* __restrict__ WU2, const float* __restrict__ aU,
    const float* __restrict__ WP1, const float* __restrict__ WP2, const float* __restrict__ aP,
    int t, int level, int ntiles)
{
    extern __shared__ float sm[];
    const int bd = blockDim.x;
    const int half = t >> 1;
    const int tile = half / ntiles;
    const int st = tile + 8;
    float* wu1d = sm;            // [ci][k][co] duplicated pairs: 1536
    float* wp1d = sm + 1536;     // 1536
    float* wu2d = sm + 3072;     // [co][ci] duplicated pairs: 512
    float* wp2d = sm + 3584;     // 512
    float* od   = sm + 4096;     // 16*st : odd -> d
    float* ev   = od + 16*st;    // 16*st : even -> c

    const int tid = threadIdx.x;
    const int ti = blockIdx.x % ntiles;
    const int bh = blockIdx.x / ntiles;
    const int b = bh / HH, h = bh % HH;
    const int lo = ti*tile, hi = lo + tile;

    const float* xin  = (level & 1) ? g_buf1 : g_buf0;
    float*       cout = (level & 1) ? g_buf0 : g_buf1;

    for (int i = tid; i < 768; i += bd) {
        int co = i & 15, k = (i >> 4) % 3, ci = i / 48;
        int gi = ((level*16 + co)*16 + ci)*3 + k;
        float wu = WU1[gi], wp = WP1[gi];
        wu1d[2*i] = wu; wu1d[2*i+1] = wu;
        wp1d[2*i] = wp; wp1d[2*i+1] = wp;
    }
    for (int i = tid; i < 256; i += bd) {
        float wu = WU2[level*256 + i], wp = WP2[level*256 + i];
        wu2d[2*i] = wu; wu2d[2*i+1] = wu;
        wp2d[2*i] = wp; wp2d[2*i+1] = wp;
    }
    const float sc = (level == 0) ? 1.f : g_scale[b];

    // de-interleave with margin 5 left / 3 right (reflect, clamped)
    for (int ci = 0; ci < 16; ci++) {
        const float2* r2 = (const float2*)(xin + (((size_t)b*16 + ci)*9 + h)*t);
        for (int m = tid; m < tile + 8; m += bd) {
            int j = lo - 5 + m;
            int jr = j < 0 ? -j : (j >= half ? 2*half - 2 - j : j);
            jr = jr < 0 ? 0 : (jr > half-1 ? half-1 : jr);
            float2 v = r2[jr];
            ev[ci*st + m] = v.x * sc;
            od[ci*st + m] = v.y * sc;
        }
    }
    __syncthreads();
    const float au = aU[level], ap = aP[level];
    const int c_lo = (lo == 0) ? 0 : lo - 1;
    const int c_hi = (hi == half) ? half : hi + 1;
    float* grb = cout + (((size_t)b*16)*9 + h) * half;

    // ---- phase 1: c = even + tanh(branchU(odd)) over [c_lo, c_hi) ----
    for (int icx = tid; icx < tile/2 + 2; icx += bd) {
        int jb = lo - 2 + icx*2;
        int m0 = icx*2 + 3;
        u64p acc2[16];
        #pragma unroll
        for (int c = 0; c < 16; c++) acc2[c] = 0ull;
        #pragma unroll
        for (int ci = 0; ci < 16; ci++) {
            const float* orow = od + ci*st + (m0 - 1);       // 8B-aligned
            float2 va = *(const float2*)orow;                // v0 v1
            float2 vb = *(const float2*)(orow + 2);          // v2 v3
            u64p d0 = pack2(va.x, va.y);                     // k=0 window
            u64p d1 = pack2(va.y, vb.x);                     // k=1
            u64p d2 = pack2(vb.x, vb.y);                     // k=2
            const ulonglong2* wrow = (const ulonglong2*)(wu1d + ci*96);
            #pragma unroll
            for (int g = 0; g < 8; g++) {
                ulonglong2 w0 = wrow[g];
                ulonglong2 w1 = wrow[8+g];
                ulonglong2 w2 = wrow[16+g];
                acc2[2*g]   = fma2(w0.x, d0, acc2[2*g]);
                acc2[2*g+1] = fma2(w0.y, d0, acc2[2*g+1]);
                acc2[2*g]   = fma2(w1.x, d1, acc2[2*g]);
                acc2[2*g+1] = fma2(w1.y, d1, acc2[2*g+1]);
                acc2[2*g]   = fma2(w2.x, d2, acc2[2*g]);
                acc2[2*g+1] = fma2(w2.y, d2, acc2[2*g+1]);
            }
        }
        #pragma unroll
        for (int co = 0; co < 16; co++) {
            float u0, u1; unpack2(acc2[co], u0, u1);
            acc2[co] = pack2(prelu_f(u0, au), prelu_f(u1, au));
        }
        bool full = (jb >= lo) && (jb + 2 <= hi);
        #pragma unroll
        for (int co = 0; co < 16; co++) {
            u64p s2 = 0ull;
            const ulonglong2* w2p = (const ulonglong2*)(wu2d + co*32);
            #pragma unroll
            for (int q = 0; q < 8; q++) {
                ulonglong2 wq = w2p[q];
                s2 = fma2(wq.x, acc2[2*q],   s2);
                s2 = fma2(wq.y, acc2[2*q+1], s2);
            }
            float s0, s1; unpack2(s2, s0, s1);
            float* erow = ev + co*st + m0;
            float c0 = erow[0] + tanh_acc(s0);
            float c1 = erow[1] + tanh_acc(s1);
            if (full) {
                erow[0] = c0; erow[1] = c1;
                float2 r; r.x = c0; r.y = c1;
                *(float2*)(grb + (size_t)co*9*half + jb) = r;
            } else {
                if (jb   >= c_lo && jb   < c_hi) { erow[0] = c0; if (jb   >= lo && jb   < hi) grb[(size_t)co*9*half + jb]   = c0; }
                if (jb+1 >= c_lo && jb+1 < c_hi) { erow[1] = c1; if (jb+1 >= lo && jb+1 < hi) grb[(size_t)co*9*half + jb+1] = c1; }
            }
        }
    }
    __syncthreads();
    if (tid < 16) {              // reflect fixups on c at global edges
        if (lo == 0)    ev[tid*st + 4]        = ev[tid*st + 6];
        if (hi == half) ev[tid*st + tile + 5] = ev[tid*st + tile + 3];
    }
    __syncthreads();

    // ---- phase 2: d = odd - tanh(branchP(c)) over [lo, hi) ----
    for (int id = tid; id < (tile >> 1); id += bd) {
        int m0 = id*2 + 5;
        u64p acc2[16];
        #pragma unroll
        for (int c = 0; c < 16; c++) acc2[c] = 0ull;
        #pragma unroll
        for (int ci = 0; ci < 16; ci++) {
            const float* erow = ev + ci*st + (m0 - 1);       // 8B-aligned
            float2 va = *(const float2*)erow;
            float2 vb = *(const float2*)(erow + 2);
            u64p d0 = pack2(va.x, va.y);
            u64p d1 = pack2(va.y, vb.x);
            u64p d2 = pack2(vb.x, vb.y);
            const ulonglong2* wrow = (const ulonglong2*)(wp1d + ci*96);
            #pragma unroll
            for (int g = 0; g < 8; g++) {
                ulonglong2 w0 = wrow[g];
                ulonglong2 w1 = wrow[8+g];
                ulonglong2 w2 = wrow[16+g];
                acc2[2*g]   = fma2(w0.x, d0, acc2[2*g]);
                acc2[2*g+1] = fma2(w0.y, d0, acc2[2*g+1]);
                acc2[2*g]   = fma2(w1.x, d1, acc2[2*g]);
                acc2[2*g+1] = fma2(w1.y, d1, acc2[2*g+1]);
                acc2[2*g]   = fma2(w2.x, d2, acc2[2*g]);
                acc2[2*g+1] = fma2(w2.y, d2, acc2[2*g+1]);
            }
        }
        #pragma unroll
        for (int co = 0; co < 16; co++) {
            float u0, u1; unpack2(acc2[co], u0, u1);
            acc2[co] = pack2(prelu_f(u0, ap), prelu_f(u1, ap));
        }
        #pragma unroll
        for (int co = 0; co < 16; co++) {
            u64p s2 = 0ull;
            const ulonglong2* w2p = (const ulonglong2*)(wp2d + co*32);
            #pragma unroll
            for (int q = 0; q < 8; q++) {
                ulonglong2 wq = w2p[q];
                s2 = fma2(wq.x, acc2[2*q],   s2);
                s2 = fma2(wq.y, acc2[2*q+1], s2);
            }
            float s0, s1; unpack2(s2, s0, s1);
            float* drow = od + co*st + m0;
            drow[0] = drow[0] - tanh_acc(s0);
            drow[1] = drow[1] - tanh_acc(s1);
        }
    }
    __syncthreads();

    // ---- row sums of c (ev) and d (od) over [lo, hi) ----
    const int warp = tid >> 5, lane = tid & 31, nw = bd >> 5;
    for (int ch = warp; ch < 16; ch += nw) {
        float s1 = 0.f, s2 = 0.f;
        for (int m = 5 + lane; m < tile + 5; m += 32) { s1 += ev[ch*st + m]; s2 += od[ch*st + m]; }
        #pragma unroll
        for (int o = 16; o > 0; o >>= 1) {
            s1 += __shfl_xor_sync(0xffffffffu, s1, o);
            s2 += __shfl_xor_sync(0xffffffffu, s2, o);
        }
        if (lane == 0) {
            g_rowsum[(ti*BB + b)*288 + ch*9 + h]       = s1;
            g_rowsum[(ti*BB + b)*288 + 144 + ch*9 + h] = s2;
        }
    }
}

// ================ gate + feats + next-level scale (levels 0..3) =============
__global__ void gate_kernel(const float* __restrict__ gumbel,
                            const float* __restrict__ Wg1, const float* __restrict__ ag1,
                            const float* __restrict__ Wg2, const float* __restrict__ ag2,
                            float* __restrict__ out, int half, int level, int ntiles)
{
    __shared__ float rs[288];
    __shared__ float pl[32];
    __shared__ float mm[4];
    const int b = blockIdx.x, tid = threadIdx.x;
    float v = g_rowsum[b*288 + tid];
    if (ntiles > 1) v += g_rowsum[BB*288 + b*288 + tid];
    rs[tid] = v;
    __syncthreads();
    if (tid < 32) {
        float s = 0.f;
        #pragma unroll
        for (int h = 0; h < 9; h++) s += rs[tid*9 + h];
        pl[tid] = s / (9.f * (float)half);
    }
    __syncthreads();
    if (tid < 2) {
        const int br = tid;
        const float a1 = ag1[level], a2 = ag2[level];
        float hm1[16];
        #pragma unroll
        for (int co = 0; co < 16; co++) {
            float s = 0.f;
            #pragma unroll
            for (int ci = 0; ci < 16; ci++)
                s = fmaf(Wg1[(level*16 + co)*16 + ci], pl[br*16 + ci], s);
            hm1[co] = prelu_f(s, a1);
        }
        float h0 = 0.f, h1 = 0.f;
        #pragma unroll
        for (int ci = 0; ci < 16; ci++) {
            h0 = fmaf(Wg2[(level*2 + 0)*16 + ci], hm1[ci], h0);
            h1 = fmaf(Wg2[(level*2 + 1)*16 + ci], hm1[ci], h1);
        }
        h0 = prelu_f(h0, a2); h1 = prelu_f(h1, a2);
        float mx = fmaxf(h0, h1);
        float e0 = expf(h0 - mx), e1 = expf(h1 - mx);
        float inv = 1.f/(e0 + e1);
        float s0 = e0*inv, s1 = e1*inv;
        const float* g = gumbel + (size_t)(level*256 + b*2 + br)*2;
        float t0 = s0 + g[0], t1 = s1 + g[1];
        mx = fmaxf(t0, t1);
        e0 = expf(t0 - mx); e1 = expf(t1 - mx);
        inv = 1.f/(e0 + e1);
        mm[br*2+0] = e0*inv;
        mm[br*2+1] = e1*inv;
    }
    __syncthreads();
    {
        float m_res = mm[(tid/144)*2 + 1];
        out[(size_t)(b*288 + tid)*9 + level] = m_res * rs[tid] / (float)half;
    }
    if (tid == 0) g_scale[b] = mm[0];
}

// ============ fused deep levels 4..8 (one CTA per batch, gates in-CTA) ======
__global__ __launch_bounds__(256) void deep_kernel(
    const float* __restrict__ WU1, const float* __restrict__ WU2, const float* __restrict__ aU,
    const float* __restrict__ WP1, const float* __restrict__ WP2, const float* __restrict__ aP,
    const float* __restrict__ Wg1, const float* __restrict__ ag1,
    const float* __restrict__ Wg2, const float* __restrict__ ag2,
    const float* __restrict__ gumbel, float* __restrict__ out)
{
    extern __shared__ float sm[];
    float* evA = sm;                 // 16*9*64
    float* odA = evA + 9216;
    float* evB = odA + 9216;         // 16*9*32
    float* odB = evB + 4608;
    float* wu1 = odB + 4608;         // 768  [ci][k][co]
    float* wp1 = wu1 + 768;
    float* wu2 = wp1 + 768;          // 256  [co][ci]
    float* wp2 = wu2 + 256;
    float* rs  = wp2 + 256;          // 288
    float* pl  = rs + 288;           // 32
    float* mm  = pl + 32;            // 4
    float* scn = mm + 4;             // 1

    const int b = blockIdx.x, tid = threadIdx.x;
    if (tid == 0) scn[0] = g_scale[b];
    __syncthreads();

    for (int L = 4; L < 9; L++) {
        const int half = 64 >> (L - 4);
        float* ev = ((L - 4) & 1) ? evB : evA;
        float* od = ((L - 4) & 1) ? odB : odA;

        for (int i = tid; i < 768; i += 256) {
            int co = i & 15, k = (i >> 4) % 3, ci = i / 48;
            int gi = ((L*16 + co)*16 + ci)*3 + k;
            wu1[i] = WU1[gi]; wp1[i] = WP1[gi];
        }
        if (tid < 256) { wu2[tid] = WU2[L*256 + tid]; wp2[tid] = WP2[L*256 + tid]; }
        const float sc = scn[0];

        if (L == 4) {
            for (int i = tid; i < 16*9*64; i += 256) {
                int j = i & 63; int r = i >> 6; int h = r % 9; int ci = r / 9;
                const float2* src = (const float2*)(g_buf0 + (((size_t)b*16 + ci)*9 + h)*128);
                float2 v = src[j];
                ev[(ci*9 + h)*64 + j] = v.x * sc;
                od[(ci*9 + h)*64 + j] = v.y * sc;
            }
        } else {
            float* pev = ((L - 5) & 1) ? evB : evA;
            int ph = half * 2;
            for (int i = tid; i < 16*9*half; i += 256) {
                int j = i % half; int r = i / half; int h = r % 9; int ci = r / 9;
                float c0 = pev[(ci*9 + h)*ph + 2*j];
                float c1 = pev[(ci*9 + h)*ph + 2*j + 1];
                ev[(ci*9 + h)*half + j] = c0 * sc;
                od[(ci*9 + h)*half + j] = c1 * sc;
            }
        }
        __syncthreads();
        const float au = aU[L], ap = aP[L];

        // phase 1: c = ev + tanh(U(od))   (float4 weight broadcasts)
        for (int it = tid; it < 9*half; it += 256) {
            int j = it % half, h = it / half;
            int jm = (j == 0) ? 1 : j - 1;
            int jp = (j == half - 1) ? half - 2 : j + 1;
            float acc[16];
            #pragma unroll
            for (int co = 0; co < 16; co++) acc[co] = 0.f;
            #pragma unroll 4
            for (int ci = 0; ci < 16; ci++) {
                const float* orow = od + (ci*9 + h)*half;
                float v0 = orow[jm], v1 = orow[j], v2 = orow[jp];
                const float* w = wu1 + ci*48;
                #pragma unroll
                for (int q = 0; q < 4; q++) {
                    float4 wk0 = ((const float4*)(w))[q];
                    float4 wk1 = ((const float4*)(w + 16))[q];
                    float4 wk2 = ((const float4*)(w + 32))[q];
                    acc[q*4+0]=fmaf(wk0.x,v0,fmaf(wk1.x,v1,fmaf(wk2.x,v2,acc[q*4+0])));
                    acc[q*4+1]=fmaf(wk0.y,v0,fmaf(wk1.y,v1,fmaf(wk2.y,v2,acc[q*4+1])));
                    acc[q*4+2]=fmaf(wk0.z,v0,fmaf(wk1.z,v1,fmaf(wk2.z,v2,acc[q*4+2])));
                    acc[q*4+3]=fmaf(wk0.w,v0,fmaf(wk1.w,v1,fmaf(wk2.w,v2,acc[q*4+3])));
                }
            }
            #pragma unroll
            for (int co = 0; co < 16; co++) acc[co] = prelu_f(acc[co], au);
            #pragma unroll
            for (int co = 0; co < 16; co++) {
                float s = 0.f;
                const float4* w4p = (const float4*)(wu2 + co*16);
                #pragma unroll
                for (int q = 0; q < 4; q++) {
                    float4 w = w4p[q];
                    s=fmaf(w.x,acc[4*q],fmaf(w.y,acc[4*q+1],fmaf(w.z,acc[4*q+2],fmaf(w.w,acc[4*q+3],s))));
                }
                ev[(co*9 + h)*half + j] += tanh_acc(s);
            }
        }
        __syncthreads();

        // phase 2: d = od - tanh(P(c))
        for (int it = tid; it < 9*half; it += 256) {
            int j = it % half, h = it / half;
            int jm = (j == 0) ? 1 : j - 1;
            int jp = (j == half - 1) ? half - 2 : j + 1;
            float acc[16];
            #pragma unroll
            for (int co = 0; co < 16; co++) acc[co] = 0.f;
            #pragma unroll 4
            for (int ci = 0; ci < 16; ci++) {
                const float* erow = ev + (ci*9 + h)*half;
                float v0 = erow[jm], v1 = erow[j], v2 = erow[jp];
                const float* w = wp1 + ci*48;
                #pragma unroll
                for (int q = 0; q < 4; q++) {
                    float4 wk0 = ((const float4*)(w))[q];
                    float4 wk1 = ((const float4*)(w + 16))[q];
                    float4 wk2 = ((const float4*)(w + 32))[q];
                    acc[q*4+0]=fmaf(wk0.x,v0,fmaf(wk1.x,v1,fmaf(wk2.x,v2,acc[q*4+0])));
                    acc[q*4+1]=fmaf(wk0.y,v0,fmaf(wk1.y,v1,fmaf(wk2.y,v2,acc[q*4+1])));
                    acc[q*4+2]=fmaf(wk0.z,v0,fmaf(wk1.z,v1,fmaf(wk2.z,v2,acc[q*4+2])));
                    acc[q*4+3]=fmaf(wk0.w,v0,fmaf(wk1.w,v1,fmaf(wk2.w,v2,acc[q*4+3])));
                }
            }
            #pragma unroll
            for (int co = 0; co < 16; co++) acc[co] = prelu_f(acc[co], ap);
            #pragma unroll
            for (int co = 0; co < 16; co++) {
                float s = 0.f;
                const float4* w4p = (const float4*)(wp2 + co*16);
                #pragma unroll
                for (int q = 0; q < 4; q++) {
                    float4 w = w4p[q];
                    s=fmaf(w.x,acc[4*q],fmaf(w.y,acc[4*q+1],fmaf(w.z,acc[4*q+2],fmaf(w.w,acc[4*q+3],s))));
                }
                od[(co*9 + h)*half + j] -= tanh_acc(s);
            }
        }
        __syncthreads();

        // row sums
        if (tid < 144) {
            int ch = tid / 9, h = tid % 9;
            float s1 = 0.f, s2 = 0.f;
            const float* er = ev + (ch*9 + h)*half;
            const float* dr = od + (ch*9 + h)*half;
            for (int j = 0; j < half; j++) { s1 += er[j]; s2 += dr[j]; }
            rs[ch*9 + h] = s1; rs[144 + ch*9 + h] = s2;
        }
        __syncthreads();
        if (tid < 32) {
            float s = 0.f;
            #pragma unroll
            for (int h = 0; h < 9; h++) s += rs[tid*9 + h];
            pl[tid] = s / (9.f * (float)half);
        }
        __syncthreads();
        if (tid < 2) {
            const int br = tid;
            const float a1 = ag1[L], a2 = ag2[L];
            float hm1[16];
            #pragma unroll
            for (int co = 0; co < 16; co++) {
                float s = 0.f;
                #pragma unroll
                for (int ci = 0; ci < 16; ci++)
                    s = fmaf(Wg1[(L*16 + co)*16 + ci], pl[br*16 + ci], s);
                hm1[co] = prelu_f(s, a1);
            }
            float h0 = 0.f, h1 = 0.f;
            #pragma unroll
            for (int ci = 0; ci < 16; ci++) {
                h0 = fmaf(Wg2[(L*2 + 0)*16 + ci], hm1[ci], h0);
                h1 = fmaf(Wg2[(L*2 + 1)*16 + ci], hm1[ci], h1);
            }
            h0 = prelu_f(h0, a2); h1 = prelu_f(h1, a2);
            float mx = fmaxf(h0, h1);
            float e0 = expf(h0 - mx), e1 = expf(h1 - mx);
            float inv = 1.f/(e0 + e1);
            float s0 = e0*inv, s1 = e1*inv;
            const float* g = gumbel + (size_t)(L*256 + b*2 + br)*2;
            float t0 = s0 + g[0], t1 = s1 + g[1];
            mx = fmaxf(t0, t1);
            e0 = expf(t0 - mx); e1 = expf(t1 - mx);
            inv = 1.f/(e0 + e1);
            mm[br*2+0] = e0*inv;
            mm[br*2+1] = e1*inv;
        }
        __syncthreads();
        for (int i = tid; i < 288; i += 256) {
            float m_res = mm[(i/144)*2 + 1];
            out[(size_t)(b*288 + i)*9 + L] = m_res * rs[i] / (float)half;
        }
        if (tid == 0) scn[0] = mm[0];
        __syncthreads();
    }
}

// =================== launch ===================
extern "C" void kernel_launch(void* const* d_in, const int* in_sizes, int n_in,
                              void* d_out, int out_size)
{
    const float* x    = (const float*)d_in[0];
    const float* gum  = (const float*)d_in[1];
    const float* Wc1  = (const float*)d_in[2];
    const float* bc1  = (const float*)d_in[3];
    const float* g1   = (const float*)d_in[4];
    const float* b1   = (const float*)d_in[5];
    const float* a1   = (const float*)d_in[6];
    const float* Wc2  = (const float*)d_in[7];
    const float* bc2  = (const float*)d_in[8];
    const float* g2   = (const float*)d_in[9];
    const float* b2   = (const float*)d_in[10];
    const float* a2   = (const float*)d_in[11];
    const float* WP1  = (const float*)d_in[12];
    const float* aP   = (const float*)d_in[13];
    const float* WP2  = (const float*)d_in[14];
    const float* WU1  = (const float*)d_in[15];
    const float* aU   = (const float*)d_in[16];
    const float* WU2  = (const float*)d_in[17];
    const float* Wg1  = (const float*)d_in[18];
    const float* ag1  = (const float*)d_in[19];
    const float* Wg2  = (const float*)d_in[20];
    const float* ag2  = (const float*)d_in[21];
    float* out = (float*)d_out;

    const int front_smem = (2512 + 16*1032) * 4;               // 76096 B
    const int lift_smem_max = (4096 + 32*(512 + 8)) * 4;       // 82944 B
    const int deep_smem = (9216*2 + 4608*2 + 768*2 + 256*2 + 288 + 32 + 4 + 4) * 4;
    cudaFuncSetAttribute(front_kernel, cudaFuncAttributeMaxDynamicSharedMemorySize, front_smem);
    cudaFuncSetAttribute(lift_kernel,  cudaFuncAttributeMaxDynamicSharedMemorySize, lift_smem_max);
    cudaFuncSetAttribute(deep_kernel,  cudaFuncAttributeMaxDynamicSharedMemorySize, deep_smem);

    front_kernel<<<BB*HH*2, 256, front_smem>>>(x, Wc1, bc1, g1, b1, a1, Wc2, bc2, g2, b2, a2);

    int t = TT;
    for (int lvl = 0; lvl < 4; lvl++) {
        const int half = t >> 1;
        const int ntiles = (lvl == 0) ? 2 : 1;
        const int tile = half / ntiles;
        const int blk = (tile >= 512) ? 256 : ((tile >= 256) ? 128 : 64);
        const int smem = (4096 + 32*(tile + 8)) * 4;
        lift_kernel<<<BB*HH*ntiles, blk, smem>>>(WU1, WU2, aU, WP1, WP2, aP, t, lvl, ntiles);
        gate_kernel<<<BB, 288>>>(gum, Wg1, ag1, Wg2, ag2, out, half, lvl, ntiles);
        t = half;
    }

    deep_kernel<<<BB, 256, deep_smem>>>(WU1, WU2, aU, WP1, WP2, aP,
                                        Wg1, ag1, Wg2, ag2, gum, out);
}

// round 15
// speedup vs baseline: 1.2774x; 1.2774x over previous
#include <cuda_runtime.h>
#include <math.h>

#define BB 128
#define CC 16
#define HH 9
#define TT 2048
#define LL 9

__device__ float g_buf0[BB*CC*HH*TT];
__device__ float g_buf1[BB*CC*HH*(TT/2)];
__device__ float g_rowsum[2*BB*2*CC*HH];
__device__ float g_scale[BB];

// accurate fast tanh: 2 MUFU + few ALU, abs err ~1e-6
__device__ __forceinline__ float tanh_acc(float x){
    float ax = fabsf(x);
    float e;
    asm("ex2.approx.f32 %0, %1;" : "=f"(e) : "f"(-2.8853900817779268f * ax));
    float r;
    asm("rcp.approx.f32 %0, %1;" : "=f"(r) : "f"(1.0f + e));
    float t = (1.0f - e) * r;
    return copysignf(t, x);
}
__device__ __forceinline__ float prelu_f(float u, float a){ return u >= 0.f ? u : a*u; }

// ====== front: conv33 + BN/PReLU + conv3 + BN/PReLU (tiled 512, 5 CTA/SM) ===
// smem = 2000 header + 16*520 ys = 41280 B -> 5 CTAs/SM (40 warps)
__global__ __launch_bounds__(256) void front_kernel(const float* __restrict__ x,
    const float* __restrict__ Wc1, const float* __restrict__ bc1,
    const float* __restrict__ g1, const float* __restrict__ b1, const float* __restrict__ a1p,
    const float* __restrict__ Wc2, const float* __restrict__ bc2,
    const float* __restrict__ g2, const float* __restrict__ b2, const float* __restrict__ a2p)
{
    extern __shared__ float sm[];
    float* wc1s = sm;          // [c][36] zero-padded (576)
    float* w2k  = sm + 576;    // [ci][k][co] (768)
    float* prm  = sm + 1344;   // 6x16 (96)
    float* xr   = sm + 1440;   // 560
    float* ys   = sm + 2000;   // 16*520

    const int tid = threadIdx.x;
    const int ti = blockIdx.x & 3;
    const int bh = blockIdx.x >> 2;
    const int b = bh / HH, h = bh % HH;
    const int lo = ti * 512;

    for (int i = tid; i < 576; i += 256) { int c = i/36, k = i%36; wc1s[i] = (k < 33) ? Wc1[c*33+k] : 0.f; }
    for (int i = tid; i < 768; i += 256) { int co = i & 15, k = (i >> 4) % 3, ci = i / 48; w2k[i] = Wc2[(co*16+ci)*3+k]; }
    if (tid < 16) {
        prm[tid]    = bc1[tid]; prm[16+tid] = g1[tid]; prm[32+tid] = b1[tid];
        prm[48+tid] = bc2[tid]; prm[64+tid] = g2[tid]; prm[80+tid] = b2[tid];
    }
    for (int m = tid; m < 560; m += 256) {
        int g = lo - 17 + m;
        xr[m] = (m < 545 && g >= 0 && g < TT) ? x[(b*HH+h)*TT + g] : 0.f;
    }
    __syncthreads();
    const float a1 = a1p[0], a2 = a2p[0];
    const float4* x4  = (const float4*)xr;
    const float4* w14 = (const float4*)wc1s;

    // conv1 over ys-relative positions [0,514): global j = lo-1 + rel
    for (int it = tid; it < 258; it += 256) {
        int q4 = it >> 1;
        int cb = (it & 1) * 8;
        float acc[8][4];
        #pragma unroll
        for (int c = 0; c < 8; c++) { acc[c][0]=0.f; acc[c][1]=0.f; acc[c][2]=0.f; acc[c][3]=0.f; }
        float4 xq = x4[q4];
        #pragma unroll
        for (int kb = 0; kb < 9; kb++) {
            float4 xn = x4[q4 + kb + 1];
            #pragma unroll
            for (int c = 0; c < 8; c++) {
                float4 w = w14[(cb + c)*9 + kb];
                acc[c][0]=fmaf(w.x,xq.x,fmaf(w.y,xq.y,fmaf(w.z,xq.z,fmaf(w.w,xq.w,acc[c][0]))));
                acc[c][1]=fmaf(w.x,xq.y,fmaf(w.y,xq.z,fmaf(w.z,xq.w,fmaf(w.w,xn.x,acc[c][1]))));
                acc[c][2]=fmaf(w.x,xq.z,fmaf(w.y,xq.w,fmaf(w.z,xn.x,fmaf(w.w,xn.y,acc[c][2]))));
                acc[c][3]=fmaf(w.x,xq.w,fmaf(w.y,xn.x,fmaf(w.z,xn.y,fmaf(w.w,xn.z,acc[c][3]))));
            }
            xq = xn;
        }
        #pragma unroll
        for (int c = 0; c < 8; c++) {
            int cc = cb + c;
            float r[4];
            #pragma unroll
            for (int p = 0; p < 4; p++) {
                int jg = lo - 1 + q4*4 + p;
                float u = (acc[c][p] + prm[cc]) * prm[16+cc] + prm[32+cc];
                r[p] = (jg >= 0 && jg < TT) ? prelu_f(u, a1) : 0.f;   // zero pad for conv2
            }
            if (q4 < 128) {
                float4 v; v.x=r[0]; v.y=r[1]; v.z=r[2]; v.w=r[3];
                *(float4*)(ys + cc*520 + q4*4) = v;
            } else {
                ys[cc*520 + 512] = r[0]; ys[cc*520 + 513] = r[1];
            }
        }
    }
    __syncthreads();

    // conv2 (1x3) over j in [lo, lo+512)
    for (int it = tid; it < 256; it += 256) {
        int id = it >> 1;
        int cb = (it & 1) * 8;
        int j0 = lo + id*4;
        float acc[8][4];
        #pragma unroll
        for (int c = 0; c < 8; c++) { acc[c][0]=0.f; acc[c][1]=0.f; acc[c][2]=0.f; acc[c][3]=0.f; }
        #pragma unroll
        for (int ci = 0; ci < 16; ci++) {
            const float* yrow = ys + ci*520 + id*4;
            float4 v03 = *(const float4*)yrow;
            float win[6]; win[0]=v03.x; win[1]=v03.y; win[2]=v03.z; win[3]=v03.w;
            win[4]=yrow[4]; win[5]=yrow[5];
            #pragma unroll
            for (int k = 0; k < 3; k++) {
                const float4* w4p = (const float4*)(w2k + ci*48 + k*16 + cb);
                #pragma unroll
                for (int q = 0; q < 2; q++) {
                    float4 w = w4p[q];
                    #pragma unroll
                    for (int p = 0; p < 4; p++) {
                        float v = win[p+k];
                        acc[q*4+0][p]=fmaf(w.x,v,acc[q*4+0][p]);
                        acc[q*4+1][p]=fmaf(w.y,v,acc[q*4+1][p]);
                        acc[q*4+2][p]=fmaf(w.z,v,acc[q*4+2][p]);
                        acc[q*4+3][p]=fmaf(w.w,v,acc[q*4+3][p]);
                    }
                }
            }
        }
        #pragma unroll
        for (int c = 0; c < 8; c++) {
            int co = cb + c;
            float4 r; float rp[4];
            #pragma unroll
            for (int p = 0; p < 4; p++) {
                float u = (acc[c][p] + prm[48+co]) * prm[64+co] + prm[80+co];
                rp[p] = prelu_f(u, a2);
            }
            r.x=rp[0]; r.y=rp[1]; r.z=rp[2]; r.w=rp[3];
            *(float4*)(g_buf0 + (((size_t)b*16 + co)*9 + h)*TT + j0) = r;
        }
    }
}

// ============= lifting level (levels 0..3, tiled, 2-pos chunks) =============
__global__ void lift_kernel(
    const float* __restrict__ WU1, const float* __restrict__ WU2, const float* __restrict__ aU,
    const float* __restrict__ WP1, const float* __restrict__ WP2, const float* __restrict__ aP,
    int t, int level, int ntiles)
{
    extern __shared__ float sm[];
    const int bd = blockDim.x;
    const int half = t >> 1;
    const int tile = half / ntiles;
    const int st = tile + 8;
    float* wu1 = sm;            // [ci][k][co]
    float* wp1 = sm + 768;
    float* wu2 = sm + 1536;     // [co][ci]
    float* wp2 = sm + 1792;
    float* od  = sm + 2048;     // 16*st : odd -> d
    float* ev  = od + 16*st;    // 16*st : even -> c

    const int tid = threadIdx.x;
    const int ti = blockIdx.x % ntiles;
    const int bh = blockIdx.x / ntiles;
    const int b = bh / HH, h = bh % HH;
    const int lo = ti*tile, hi = lo + tile;

    const float* xin  = (level & 1) ? g_buf1 : g_buf0;
    float*       cout = (level & 1) ? g_buf0 : g_buf1;

    for (int i = tid; i < 768; i += bd) {
        int co = i & 15, k = (i >> 4) % 3, ci = i / 48;
        int gi = ((level*16 + co)*16 + ci)*3 + k;
        wu1[i] = WU1[gi]; wp1[i] = WP1[gi];
    }
    for (int i = tid; i < 256; i += bd) { wu2[i] = WU2[level*256 + i]; wp2[i] = WP2[level*256 + i]; }
    const float sc = (level == 0) ? 1.f : g_scale[b];

    // de-interleave with margin 5 left / 3 right (reflect, clamped)
    for (int ci = 0; ci < 16; ci++) {
        const float2* r2 = (const float2*)(xin + (((size_t)b*16 + ci)*9 + h)*t);
        for (int m = tid; m < tile + 8; m += bd) {
            int j = lo - 5 + m;
            int jr = j < 0 ? -j : (j >= half ? 2*half - 2 - j : j);
            jr = jr < 0 ? 0 : (jr > half-1 ? half-1 : jr);
            float2 v = r2[jr];
            ev[ci*st + m] = v.x * sc;
            od[ci*st + m] = v.y * sc;
        }
    }
    __syncthreads();
    const float au = aU[level], ap = aP[level];
    const int c_lo = (lo == 0) ? 0 : lo - 1;
    const int c_hi = (hi == half) ? half : hi + 1;
    float* grb = cout + (((size_t)b*16)*9 + h) * half;

    // ---- phase 1: c = even + tanh(branchU(odd)) over [c_lo, c_hi) ----
    for (int icx = tid; icx < tile/2 + 2; icx += bd) {
        int jb = lo - 2 + icx*2;
        int m0 = icx*2 + 3;
        float acc[16][2];
        #pragma unroll
        for (int c = 0; c < 16; c++) { acc[c][0]=0.f; acc[c][1]=0.f; }
        #pragma unroll
        for (int ci = 0; ci < 16; ci++) {
            const float* orow = od + ci*st + (m0 - 1);
            float2 va = *(const float2*)orow;        // v0 v1
            float2 vb = *(const float2*)(orow + 2);  // v2 v3
            float w0a = va.x, w0b = va.y;            // k=0 window
            float w1a = va.y, w1b = vb.x;            // k=1
            float w2a = vb.x, w2b = vb.y;            // k=2
            const float* w = wu1 + ci*48;
            #pragma unroll
            for (int q = 0; q < 4; q++) {
                float4 wk0 = ((const float4*)(w))[q];
                float4 wk1 = ((const float4*)(w + 16))[q];
                float4 wk2 = ((const float4*)(w + 32))[q];
                acc[q*4+0][0]=fmaf(wk0.x,w0a,fmaf(wk1.x,w1a,fmaf(wk2.x,w2a,acc[q*4+0][0])));
                acc[q*4+0][1]=fmaf(wk0.x,w0b,fmaf(wk1.x,w1b,fmaf(wk2.x,w2b,acc[q*4+0][1])));
                acc[q*4+1][0]=fmaf(wk0.y,w0a,fmaf(wk1.y,w1a,fmaf(wk2.y,w2a,acc[q*4+1][0])));
                acc[q*4+1][1]=fmaf(wk0.y,w0b,fmaf(wk1.y,w1b,fmaf(wk2.y,w2b,acc[q*4+1][1])));
                acc[q*4+2][0]=fmaf(wk0.z,w0a,fmaf(wk1.z,w1a,fmaf(wk2.z,w2a,acc[q*4+2][0])));
                acc[q*4+2][1]=fmaf(wk0.z,w0b,fmaf(wk1.z,w1b,fmaf(wk2.z,w2b,acc[q*4+2][1])));
                acc[q*4+3][0]=fmaf(wk0.w,w0a,fmaf(wk1.w,w1a,fmaf(wk2.w,w2a,acc[q*4+3][0])));
                acc[q*4+3][1]=fmaf(wk0.w,w0b,fmaf(wk1.w,w1b,fmaf(wk2.w,w2b,acc[q*4+3][1])));
            }
        }
        #pragma unroll
        for (int co = 0; co < 16; co++) { acc[co][0] = prelu_f(acc[co][0], au); acc[co][1] = prelu_f(acc[co][1], au); }
        bool full = (jb >= lo) && (jb + 2 <= hi);
        #pragma unroll
        for (int co = 0; co < 16; co++) {
            float s0 = 0.f, s1 = 0.f;
            const float4* w4p = (const float4*)(wu2 + co*16);
            #pragma unroll
            for (int q = 0; q < 4; q++) {
                float4 w = w4p[q];
                s0=fmaf(w.x,acc[4*q][0],fmaf(w.y,acc[4*q+1][0],fmaf(w.z,acc[4*q+2][0],fmaf(w.w,acc[4*q+3][0],s0))));
                s1=fmaf(w.x,acc[4*q][1],fmaf(w.y,acc[4*q+1][1],fmaf(w.z,acc[4*q+2][1],fmaf(w.w,acc[4*q+3][1],s1))));
            }
            float* erow = ev + co*st + m0;
            float c0 = erow[0] + tanh_acc(s0);
            float c1 = erow[1] + tanh_acc(s1);
            if (full) {
                erow[0] = c0; erow[1] = c1;
                float2 r; r.x = c0; r.y = c1;
                *(float2*)(grb + (size_t)co*9*half + jb) = r;
            } else {
                if (jb   >= c_lo && jb   < c_hi) { erow[0] = c0; if (jb   >= lo && jb   < hi) grb[(size_t)co*9*half + jb]   = c0; }
                if (jb+1 >= c_lo && jb+1 < c_hi) { erow[1] = c1; if (jb+1 >= lo && jb+1 < hi) grb[(size_t)co*9*half + jb+1] = c1; }
            }
        }
    }
    __syncthreads();
    if (tid < 16) {              // reflect fixups on c at global edges
        if (lo == 0)    ev[tid*st + 4]        = ev[tid*st + 6];
        if (hi == half) ev[tid*st + tile + 5] = ev[tid*st + tile + 3];
    }
    __syncthreads();

    // ---- phase 2: d = odd - tanh(branchP(c)) over [lo, hi) ----
    for (int id = tid; id < (tile >> 1); id += bd) {
        int m0 = id*2 + 5;
        float acc[16][2];
        #pragma unroll
        for (int c = 0; c < 16; c++) { acc[c][0]=0.f; acc[c][1]=0.f; }
        #pragma unroll
        for (int ci = 0; ci < 16; ci++) {
            const float* erow = ev + ci*st + (m0 - 1);
            float2 va = *(const float2*)erow;
            float2 vb = *(const float2*)(erow + 2);
            float w0a = va.x, w0b = va.y;
            float w1a = va.y, w1b = vb.x;
            float w2a = vb.x, w2b = vb.y;
            const float* w = wp1 + ci*48;
            #pragma unroll
            for (int q = 0; q < 4; q++) {
                float4 wk0 = ((const float4*)(w))[q];
                float4 wk1 = ((const float4*)(w + 16))[q];
                float4 wk2 = ((const float4*)(w + 32))[q];
                acc[q*4+0][0]=fmaf(wk0.x,w0a,fmaf(wk1.x,w1a,fmaf(wk2.x,w2a,acc[q*4+0][0])));
                acc[q*4+0][1]=fmaf(wk0.x,w0b,fmaf(wk1.x,w1b,fmaf(wk2.x,w2b,acc[q*4+0][1])));
                acc[q*4+1][0]=fmaf(wk0.y,w0a,fmaf(wk1.y,w1a,fmaf(wk2.y,w2a,acc[q*4+1][0])));
                acc[q*4+1][1]=fmaf(wk0.y,w0b,fmaf(wk1.y,w1b,fmaf(wk2.y,w2b,acc[q*4+1][1])));
                acc[q*4+2][0]=fmaf(wk0.z,w0a,fmaf(wk1.z,w1a,fmaf(wk2.z,w2a,acc[q*4+2][0])));
                acc[q*4+2][1]=fmaf(wk0.z,w0b,fmaf(wk1.z,w1b,fmaf(wk2.z,w2b,acc[q*4+2][1])));
                acc[q*4+3][0]=fmaf(wk0.w,w0a,fmaf(wk1.w,w1a,fmaf(wk2.w,w2a,acc[q*4+3][0])));
                acc[q*4+3][1]=fmaf(wk0.w,w0b,fmaf(wk1.w,w1b,fmaf(wk2.w,w2b,acc[q*4+3][1])));
            }
        }
        #pragma unroll
        for (int co = 0; co < 16; co++) { acc[co][0] = prelu_f(acc[co][0], ap); acc[co][1] = prelu_f(acc[co][1], ap); }
        #pragma unroll
        for (int co = 0; co < 16; co++) {
            float s0 = 0.f, s1 = 0.f;
            const float4* w4p = (const float4*)(wp2 + co*16);
            #pragma unroll
            for (int q = 0; q < 4; q++) {
                float4 w = w4p[q];
                s0=fmaf(w.x,acc[4*q][0],fmaf(w.y,acc[4*q+1][0],fmaf(w.z,acc[4*q+2][0],fmaf(w.w,acc[4*q+3][0],s0))));
                s1=fmaf(w.x,acc[4*q][1],fmaf(w.y,acc[4*q+1][1],fmaf(w.z,acc[4*q+2][1],fmaf(w.w,acc[4*q+3][1],s1))));
            }
            float* drow = od + co*st + m0;
            drow[0] = drow[0] - tanh_acc(s0);
            drow[1] = drow[1] - tanh_acc(s1);
        }
    }
    __syncthreads();

    // ---- row sums of c (ev) and d (od) over [lo, hi) ----
    const int warp = tid >> 5, lane = tid & 31, nw = bd >> 5;
    for (int ch = warp; ch < 16; ch += nw) {
        float s1 = 0.f, s2 = 0.f;
        for (int m = 5 + lane; m < tile + 5; m += 32) { s1 += ev[ch*st + m]; s2 += od[ch*st + m]; }
        #pragma unroll
        for (int o = 16; o > 0; o >>= 1) {
            s1 += __shfl_xor_sync(0xffffffffu, s1, o);
            s2 += __shfl_xor_sync(0xffffffffu, s2, o);
        }
        if (lane == 0) {
            g_rowsum[(ti*BB + b)*288 + ch*9 + h]       = s1;
            g_rowsum[(ti*BB + b)*288 + 144 + ch*9 + h] = s2;
        }
    }
}

// ================ gate + feats + next-level scale (levels 0..3) =============
__global__ void gate_kernel(const float* __restrict__ gumbel,
                            const float* __restrict__ Wg1, const float* __restrict__ ag1,
                            const float* __restrict__ Wg2, const float* __restrict__ ag2,
                            float* __restrict__ out, int half, int level, int ntiles)
{
    __shared__ float rs[288];
    __shared__ float pl[32];
    __shared__ float mm[4];
    const int b = blockIdx.x, tid = threadIdx.x;
    float v = g_rowsum[b*288 + tid];
    if (ntiles > 1) v += g_rowsum[BB*288 + b*288 + tid];
    rs[tid] = v;
    __syncthreads();
    if (tid < 32) {
        float s = 0.f;
        #pragma unroll
        for (int h = 0; h < 9; h++) s += rs[tid*9 + h];
        pl[tid] = s / (9.f * (float)half);
    }
    __syncthreads();
    if (tid < 2) {
        const int br = tid;
        const float a1 = ag1[level], a2 = ag2[level];
        float hm1[16];
        #pragma unroll
        for (int co = 0; co < 16; co++) {
            float s = 0.f;
            #pragma unroll
            for (int ci = 0; ci < 16; ci++)
                s = fmaf(Wg1[(level*16 + co)*16 + ci], pl[br*16 + ci], s);
            hm1[co] = prelu_f(s, a1);
        }
        float h0 = 0.f, h1 = 0.f;
        #pragma unroll
        for (int ci = 0; ci < 16; ci++) {
            h0 = fmaf(Wg2[(level*2 + 0)*16 + ci], hm1[ci], h0);
            h1 = fmaf(Wg2[(level*2 + 1)*16 + ci], hm1[ci], h1);
        }
        h0 = prelu_f(h0, a2); h1 = prelu_f(h1, a2);
        float mx = fmaxf(h0, h1);
        float e0 = expf(h0 - mx), e1 = expf(h1 - mx);
        float inv = 1.f/(e0 + e1);
        float s0 = e0*inv, s1 = e1*inv;
        const float* g = gumbel + (size_t)(level*256 + b*2 + br)*2;
        float t0 = s0 + g[0], t1 = s1 + g[1];
        mx = fmaxf(t0, t1);
        e0 = expf(t0 - mx); e1 = expf(t1 - mx);
        inv = 1.f/(e0 + e1);
        mm[br*2+0] = e0*inv;
        mm[br*2+1] = e1*inv;
    }
    __syncthreads();
    {
        float m_res = mm[(tid/144)*2 + 1];
        out[(size_t)(b*288 + tid)*9 + level] = m_res * rs[tid] / (float)half;
    }
    if (tid == 0) g_scale[b] = mm[0];
}

// ============ fused deep levels 4..8 (one CTA per batch, gates in-CTA) ======
__global__ __launch_bounds__(256) void deep_kernel(
    const float* __restrict__ WU1, const float* __restrict__ WU2, const float* __restrict__ aU,
    const float* __restrict__ WP1, const float* __restrict__ WP2, const float* __restrict__ aP,
    const float* __restrict__ Wg1, const float* __restrict__ ag1,
    const float* __restrict__ Wg2, const float* __restrict__ ag2,
    const float* __restrict__ gumbel, float* __restrict__ out)
{
    extern __shared__ float sm[];
    float* evA = sm;                 // 16*9*64
    float* odA = evA + 9216;
    float* evB = odA + 9216;         // 16*9*32
    float* odB = evB + 4608;
    float* wu1 = odB + 4608;         // 768  [ci][k][co]
    float* wp1 = wu1 + 768;
    float* wu2 = wp1 + 768;          // 256  [co][ci]
    float* wp2 = wu2 + 256;
    float* rs  = wp2 + 256;          // 288
    float* pl  = rs + 288;           // 32
    float* mm  = pl + 32;            // 4
    float* scn = mm + 4;             // 1

    const int b = blockIdx.x, tid = threadIdx.x;
    if (tid == 0) scn[0] = g_scale[b];
    __syncthreads();

    for (int L = 4; L < 9; L++) {
        const int half = 64 >> (L - 4);
        float* ev = ((L - 4) & 1) ? evB : evA;
        float* od = ((L - 4) & 1) ? odB : odA;

        for (int i = tid; i < 768; i += 256) {
            int co = i & 15, k = (i >> 4) % 3, ci = i / 48;
            int gi = ((L*16 + co)*16 + ci)*3 + k;
            wu1[i] = WU1[gi]; wp1[i] = WP1[gi];
        }
        if (tid < 256) { wu2[tid] = WU2[L*256 + tid]; wp2[tid] = WP2[L*256 + tid]; }
        const float sc = scn[0];

        if (L == 4) {
            for (int i = tid; i < 16*9*64; i += 256) {
                int j = i & 63; int r = i >> 6; int h = r % 9; int ci = r / 9;
                const float2* src = (const float2*)(g_buf0 + (((size_t)b*16 + ci)*9 + h)*128);
                float2 v = src[j];
                ev[(ci*9 + h)*64 + j] = v.x * sc;
                od[(ci*9 + h)*64 + j] = v.y * sc;
            }
        } else {
            float* pev = ((L - 5) & 1) ? evB : evA;
            int ph = half * 2;
            for (int i = tid; i < 16*9*half; i += 256) {
                int j = i % half; int r = i / half; int h = r % 9; int ci = r / 9;
                float c0 = pev[(ci*9 + h)*ph + 2*j];
                float c1 = pev[(ci*9 + h)*ph + 2*j + 1];
                ev[(ci*9 + h)*half + j] = c0 * sc;
                od[(ci*9 + h)*half + j] = c1 * sc;
            }
        }
        __syncthreads();
        const float au = aU[L], ap = aP[L];

        // phase 1: c = ev + tanh(U(od))   (float4 weight broadcasts)
        for (int it = tid; it < 9*half; it += 256) {
            int j = it % half, h = it / half;
            int jm = (j == 0) ? 1 : j - 1;
            int jp = (j == half - 1) ? half - 2 : j + 1;
            float acc[16];
            #pragma unroll
            for (int co = 0; co < 16; co++) acc[co] = 0.f;
            #pragma unroll 4
            for (int ci = 0; ci < 16; ci++) {
                const float* orow = od + (ci*9 + h)*half;
                float v0 = orow[jm], v1 = orow[j], v2 = orow[jp];
                const float* w = wu1 + ci*48;
                #pragma unroll
                for (int q = 0; q < 4; q++) {
                    float4 wk0 = ((const float4*)(w))[q];
                    float4 wk1 = ((const float4*)(w + 16))[q];
                    float4 wk2 = ((const float4*)(w + 32))[q];
                    acc[q*4+0]=fmaf(wk0.x,v0,fmaf(wk1.x,v1,fmaf(wk2.x,v2,acc[q*4+0])));
                    acc[q*4+1]=fmaf(wk0.y,v0,fmaf(wk1.y,v1,fmaf(wk2.y,v2,acc[q*4+1])));
                    acc[q*4+2]=fmaf(wk0.z,v0,fmaf(wk1.z,v1,fmaf(wk2.z,v2,acc[q*4+2])));
                    acc[q*4+3]=fmaf(wk0.w,v0,fmaf(wk1.w,v1,fmaf(wk2.w,v2,acc[q*4+3])));
                }
            }
            #pragma unroll
            for (int co = 0; co < 16; co++) acc[co] = prelu_f(acc[co], au);
            #pragma unroll
            for (int co = 0; co < 16; co++) {
                float s = 0.f;
                const float4* w4p = (const float4*)(wu2 + co*16);
                #pragma unroll
                for (int q = 0; q < 4; q++) {
                    float4 w = w4p[q];
                    s=fmaf(w.x,acc[4*q],fmaf(w.y,acc[4*q+1],fmaf(w.z,acc[4*q+2],fmaf(w.w,acc[4*q+3],s))));
                }
                ev[(co*9 + h)*half + j] += tanh_acc(s);
            }
        }
        __syncthreads();

        // phase 2: d = od - tanh(P(c))
        for (int it = tid; it < 9*half; it += 256) {
            int j = it % half, h = it / half;
            int jm = (j == 0) ? 1 : j - 1;
            int jp = (j == half - 1) ? half - 2 : j + 1;
            float acc[16];
            #pragma unroll
            for (int co = 0; co < 16; co++) acc[co] = 0.f;
            #pragma unroll 4
            for (int ci = 0; ci < 16; ci++) {
                const float* erow = ev + (ci*9 + h)*half;
                float v0 = erow[jm], v1 = erow[j], v2 = erow[jp];
                const float* w = wp1 + ci*48;
                #pragma unroll
                for (int q = 0; q < 4; q++) {
                    float4 wk0 = ((const float4*)(w))[q];
                    float4 wk1 = ((const float4*)(w + 16))[q];
                    float4 wk2 = ((const float4*)(w + 32))[q];
                    acc[q*4+0]=fmaf(wk0.x,v0,fmaf(wk1.x,v1,fmaf(wk2.x,v2,acc[q*4+0])));
                    acc[q*4+1]=fmaf(wk0.y,v0,fmaf(wk1.y,v1,fmaf(wk2.y,v2,acc[q*4+1])));
                    acc[q*4+2]=fmaf(wk0.z,v0,fmaf(wk1.z,v1,fmaf(wk2.z,v2,acc[q*4+2])));
                    acc[q*4+3]=fmaf(wk0.w,v0,fmaf(wk1.w,v1,fmaf(wk2.w,v2,acc[q*4+3])));
                }
            }
            #pragma unroll
            for (int co = 0; co < 16; co++) acc[co] = prelu_f(acc[co], ap);
            #pragma unroll
            for (int co = 0; co < 16; co++) {
                float s = 0.f;
                const float4* w4p = (const float4*)(wp2 + co*16);
                #pragma unroll
                for (int q = 0; q < 4; q++) {
                    float4 w = w4p[q];
                    s=fmaf(w.x,acc[4*q],fmaf(w.y,acc[4*q+1],fmaf(w.z,acc[4*q+2],fmaf(w.w,acc[4*q+3],s))));
                }
                od[(co*9 + h)*half + j] -= tanh_acc(s);
            }
        }
        __syncthreads();

        // row sums
        if (tid < 144) {
            int ch = tid / 9, h = tid % 9;
            float s1 = 0.f, s2 = 0.f;
            const float* er = ev + (ch*9 + h)*half;
            const float* dr = od + (ch*9 + h)*half;
            for (int j = 0; j < half; j++) { s1 += er[j]; s2 += dr[j]; }
            rs[ch*9 + h] = s1; rs[144 + ch*9 + h] = s2;
        }
        __syncthreads();
        if (tid < 32) {
            float s = 0.f;
            #pragma unroll
            for (int h = 0; h < 9; h++) s += rs[tid*9 + h];
            pl[tid] = s / (9.f * (float)half);
        }
        __syncthreads();
        if (tid < 2) {
            const int br = tid;
            const float a1 = ag1[L], a2 = ag2[L];
            float hm1[16];
            #pragma unroll
            for (int co = 0; co < 16; co++) {
                float s = 0.f;
                #pragma unroll
                for (int ci = 0; ci < 16; ci++)
                    s = fmaf(Wg1[(L*16 + co)*16 + ci], pl[br*16 + ci], s);
                hm1[co] = prelu_f(s, a1);
            }
            float h0 = 0.f, h1 = 0.f;
            #pragma unroll
            for (int ci = 0; ci < 16; ci++) {
                h0 = fmaf(Wg2[(L*2 + 0)*16 + ci], hm1[ci], h0);
                h1 = fmaf(Wg2[(L*2 + 1)*16 + ci], hm1[ci], h1);
            }
            h0 = prelu_f(h0, a2); h1 = prelu_f(h1, a2);
            float mx = fmaxf(h0, h1);
            float e0 = expf(h0 - mx), e1 = expf(h1 - mx);
            float inv = 1.f/(e0 + e1);
            float s0 = e0*inv, s1 = e1*inv;
            const float* g = gumbel + (size_t)(L*256 + b*2 + br)*2;
            float t0 = s0 + g[0], t1 = s1 + g[1];
            mx = fmaxf(t0, t1);
            e0 = expf(t0 - mx); e1 = expf(t1 - mx);
            inv = 1.f/(e0 + e1);
            mm[br*2+0] = e0*inv;
            mm[br*2+1] = e1*inv;
        }
        __syncthreads();
        for (int i = tid; i < 288; i += 256) {
            float m_res = mm[(i/144)*2 + 1];
            out[(size_t)(b*288 + i)*9 + L] = m_res * rs[i] / (float)half;
        }
        if (tid == 0) scn[0] = mm[0];
        __syncthreads();
    }
}

// =================== launch ===================
extern "C" void kernel_launch(void* const* d_in, const int* in_sizes, int n_in,
                              void* d_out, int out_size)
{
    const float* x    = (const float*)d_in[0];
    const float* gum  = (const float*)d_in[1];
    const float* Wc1  = (const float*)d_in[2];
    const float* bc1  = (const float*)d_in[3];
    const float* g1   = (const float*)d_in[4];
    const float* b1   = (const float*)d_in[5];
    const float* a1   = (const float*)d_in[6];
    const float* Wc2  = (const float*)d_in[7];
    const float* bc2  = (const float*)d_in[8];
    const float* g2   = (const float*)d_in[9];
    const float* b2   = (const float*)d_in[10];
    const float* a2   = (const float*)d_in[11];
    const float* WP1  = (const float*)d_in[12];
    const float* aP   = (const float*)d_in[13];
    const float* WP2  = (const float*)d_in[14];
    const float* WU1  = (const float*)d_in[15];
    const float* aU   = (const float*)d_in[16];
    const float* WU2  = (const float*)d_in[17];
    const float* Wg1  = (const float*)d_in[18];
    const float* ag1  = (const float*)d_in[19];
    const float* Wg2  = (const float*)d_in[20];
    const float* ag2  = (const float*)d_in[21];
    float* out = (float*)d_out;

    const int front_smem = (2000 + 16*520) * 4;                // 41280 B -> 5 CTAs/SM
    const int lift_smem_max = (2048 + 32*(512 + 8)) * 4;       // 74752 B
    const int deep_smem = (9216*2 + 4608*2 + 768*2 + 256*2 + 288 + 32 + 4 + 4) * 4;
    cudaFuncSetAttribute(front_kernel, cudaFuncAttributeMaxDynamicSharedMemorySize, front_smem);
    cudaFuncSetAttribute(lift_kernel,  cudaFuncAttributeMaxDynamicSharedMemorySize, lift_smem_max);
    cudaFuncSetAttribute(deep_kernel,  cudaFuncAttributeMaxDynamicSharedMemorySize, deep_smem);

    front_kernel<<<BB*HH*4, 256, front_smem>>>(x, Wc1, bc1, g1, b1, a1, Wc2, bc2, g2, b2, a2);

    int t = TT;
    for (int lvl = 0; lvl < 4; lvl++) {
        const int half = t >> 1;
        const int ntiles = (lvl <= 1) ? 2 : 1;     // L0 tile 512, L1 tile 256
        const int tile = half / ntiles;
        const int chunks = tile/2 + 2;
        int blk = ((chunks + 31) / 32) * 32;
        if (blk > 256) blk = 256;
        if (blk < 64) blk = 64;
        const int smem = (2048 + 32*(tile + 8)) * 4;
        lift_kernel<<<BB*HH*ntiles, blk, smem>>>(WU1, WU2, aU, WP1, WP2, aP, t, lvl, ntiles);
        gate_kernel<<<BB, 288>>>(gum, Wg1, ag1, Wg2, ag2, out, half, lvl, ntiles);
        t = half;
    }

    deep_kernel<<<BB, 256, deep_smem>>>(WU1, WU2, aU, WP1, WP2, aP,
                                        Wg1, ag1, Wg2, ag2, gum, out);
}

// round 16
// speedup vs baseline: 1.2957x; 1.0143x over previous
#include <cuda_runtime.h>
#include <math.h>

#define BB 128
#define CC 16
#define HH 9
#define TT 2048
#define LL 9

__device__ float g_buf0[BB*CC*HH*TT];
__device__ float g_buf1[BB*CC*HH*(TT/2)];
__device__ float g_rowsum[2*BB*2*CC*HH];
__device__ float g_scale[BB];

// accurate fast tanh: 2 MUFU + few ALU, abs err ~1e-6
__device__ __forceinline__ float tanh_acc(float x){
    float ax = fabsf(x);
    float e;
    asm("ex2.approx.f32 %0, %1;" : "=f"(e) : "f"(-2.8853900817779268f * ax));
    float r;
    asm("rcp.approx.f32 %0, %1;" : "=f"(r) : "f"(1.0f + e));
    float t = (1.0f - e) * r;
    return copysignf(t, x);
}
__device__ __forceinline__ float prelu_f(float u, float a){ return u >= 0.f ? u : a*u; }

// ====== front: conv33 + BN/PReLU + conv3 + BN/PReLU (tiled 512, 5 CTA/SM) ===
__global__ __launch_bounds__(256) void front_kernel(const float* __restrict__ x,
    const float* __restrict__ Wc1, const float* __restrict__ bc1,
    const float* __restrict__ g1, const float* __restrict__ b1, const float* __restrict__ a1p,
    const float* __restrict__ Wc2, const float* __restrict__ bc2,
    const float* __restrict__ g2, const float* __restrict__ b2, const float* __restrict__ a2p)
{
    extern __shared__ float sm[];
    float* wc1s = sm;          // [c][36] zero-padded (576)
    float* w2k  = sm + 576;    // [ci][k][co] (768)
    float* prm  = sm + 1344;   // 6x16 (96)
    float* xr   = sm + 1440;   // 560
    float* ys   = sm + 2000;   // 16*520

    const int tid = threadIdx.x;
    const int ti = blockIdx.x & 3;
    const int bh = blockIdx.x >> 2;
    const int b = bh / HH, h = bh % HH;
    const int lo = ti * 512;

    for (int i = tid; i < 576; i += 256) { int c = i/36, k = i%36; wc1s[i] = (k < 33) ? Wc1[c*33+k] : 0.f; }
    for (int i = tid; i < 768; i += 256) { int co = i & 15, k = (i >> 4) % 3, ci = i / 48; w2k[i] = Wc2[(co*16+ci)*3+k]; }
    if (tid < 16) {
        prm[tid]    = bc1[tid]; prm[16+tid] = g1[tid]; prm[32+tid] = b1[tid];
        prm[48+tid] = bc2[tid]; prm[64+tid] = g2[tid]; prm[80+tid] = b2[tid];
    }
    for (int m = tid; m < 560; m += 256) {
        int g = lo - 17 + m;
        xr[m] = (m < 546 && g >= 0 && g < TT) ? x[(b*HH+h)*TT + g] : 0.f;   // FIX: 546 (=512+34)
    }
    __syncthreads();
    const float a1 = a1p[0], a2 = a2p[0];
    const float4* x4  = (const float4*)xr;
    const float4* w14 = (const float4*)wc1s;

    // conv1 over ys-relative positions [0,514): global j = lo-1 + rel
    for (int it = tid; it < 258; it += 256) {
        int q4 = it >> 1;
        int cb = (it & 1) * 8;
        float acc[8][4];
        #pragma unroll
        for (int c = 0; c < 8; c++) { acc[c][0]=0.f; acc[c][1]=0.f; acc[c][2]=0.f; acc[c][3]=0.f; }
        float4 xq = x4[q4];
        #pragma unroll
        for (int kb = 0; kb < 9; kb++) {
            float4 xn = x4[q4 + kb + 1];
            #pragma unroll
            for (int c = 0; c < 8; c++) {
                float4 w = w14[(cb + c)*9 + kb];
                acc[c][0]=fmaf(w.x,xq.x,fmaf(w.y,xq.y,fmaf(w.z,xq.z,fmaf(w.w,xq.w,acc[c][0]))));
                acc[c][1]=fmaf(w.x,xq.y,fmaf(w.y,xq.z,fmaf(w.z,xq.w,fmaf(w.w,xn.x,acc[c][1]))));
                acc[c][2]=fmaf(w.x,xq.z,fmaf(w.y,xq.w,fmaf(w.z,xn.x,fmaf(w.w,xn.y,acc[c][2]))));
                acc[c][3]=fmaf(w.x,xq.w,fmaf(w.y,xn.x,fmaf(w.z,xn.y,fmaf(w.w,xn.z,acc[c][3]))));
            }
            xq = xn;
        }
        #pragma unroll
        for (int c = 0; c < 8; c++) {
            int cc = cb + c;
            float r[4];
            #pragma unroll
            for (int p = 0; p < 4; p++) {
                int jg = lo - 1 + q4*4 + p;
                float u = (acc[c][p] + prm[cc]) * prm[16+cc] + prm[32+cc];
                r[p] = (jg >= 0 && jg < TT) ? prelu_f(u, a1) : 0.f;   // zero pad for conv2
            }
            if (q4 < 128) {
                float4 v; v.x=r[0]; v.y=r[1]; v.z=r[2]; v.w=r[3];
                *(float4*)(ys + cc*520 + q4*4) = v;
            } else {
                ys[cc*520 + 512] = r[0]; ys[cc*520 + 513] = r[1];
            }
        }
    }
    __syncthreads();

    // conv2 (1x3) over j in [lo, lo+512)
    for (int it = tid; it < 256; it += 256) {
        int id = it >> 1;
        int cb = (it & 1) * 8;
        int j0 = lo + id*4;
        float acc[8][4];
        #pragma unroll
        for (int c = 0; c < 8; c++) { acc[c][0]=0.f; acc[c][1]=0.f; acc[c][2]=0.f; acc[c][3]=0.f; }
        #pragma unroll
        for (int ci = 0; ci < 16; ci++) {
            const float* yrow = ys + ci*520 + id*4;
            float4 v03 = *(const float4*)yrow;
            float win[6]; win[0]=v03.x; win[1]=v03.y; win[2]=v03.z; win[3]=v03.w;
            win[4]=yrow[4]; win[5]=yrow[5];
            #pragma unroll
            for (int k = 0; k < 3; k++) {
                const float4* w4p = (const float4*)(w2k + ci*48 + k*16 + cb);
                #pragma unroll
                for (int q = 0; q < 2; q++) {
                    float4 w = w4p[q];
                    #pragma unroll
                    for (int p = 0; p < 4; p++) {
                        float v = win[p+k];
                        acc[q*4+0][p]=fmaf(w.x,v,acc[q*4+0][p]);
                        acc[q*4+1][p]=fmaf(w.y,v,acc[q*4+1][p]);
                        acc[q*4+2][p]=fmaf(w.z,v,acc[q*4+2][p]);
                        acc[q*4+3][p]=fmaf(w.w,v,acc[q*4+3][p]);
                    }
                }
            }
        }
        #pragma unroll
        for (int c = 0; c < 8; c++) {
            int co = cb + c;
            float4 r; float rp[4];
            #pragma unroll
            for (int p = 0; p < 4; p++) {
                float u = (acc[c][p] + prm[48+co]) * prm[64+co] + prm[80+co];
                rp[p] = prelu_f(u, a2);
            }
            r.x=rp[0]; r.y=rp[1]; r.z=rp[2]; r.w=rp[3];
            *(float4*)(g_buf0 + (((size_t)b*16 + co)*9 + h)*TT + j0) = r;
        }
    }
}

// ============= lifting level (levels 0..3, tiled, 2-pos chunks) =============
__global__ void lift_kernel(
    const float* __restrict__ WU1, const float* __restrict__ WU2, const float* __restrict__ aU,
    const float* __restrict__ WP1, const float* __restrict__ WP2, const float* __restrict__ aP,
    int t, int level, int ntiles)
{
    extern __shared__ float sm[];
    const int bd = blockDim.x;
    const int half = t >> 1;
    const int tile = half / ntiles;
    const int st = tile + 8;
    float* wu1 = sm;            // [ci][k][co]
    float* wp1 = sm + 768;
    float* wu2 = sm + 1536;     // [co][ci]
    float* wp2 = sm + 1792;
    float* od  = sm + 2048;     // 16*st : odd -> d
    float* ev  = od + 16*st;    // 16*st : even -> c

    const int tid = threadIdx.x;
    const int ti = blockIdx.x % ntiles;
    const int bh = blockIdx.x / ntiles;
    const int b = bh / HH, h = bh % HH;
    const int lo = ti*tile, hi = lo + tile;

    const float* xin  = (level & 1) ? g_buf1 : g_buf0;
    float*       cout = (level & 1) ? g_buf0 : g_buf1;

    for (int i = tid; i < 768; i += bd) {
        int co = i & 15, k = (i >> 4) % 3, ci = i / 48;
        int gi = ((level*16 + co)*16 + ci)*3 + k;
        wu1[i] = WU1[gi]; wp1[i] = WP1[gi];
    }
    for (int i = tid; i < 256; i += bd) { wu2[i] = WU2[level*256 + i]; wp2[i] = WP2[level*256 + i]; }
    const float sc = (level == 0) ? 1.f : g_scale[b];

    // de-interleave with margin 5 left / 3 right (reflect, clamped)
    for (int ci = 0; ci < 16; ci++) {
        const float2* r2 = (const float2*)(xin + (((size_t)b*16 + ci)*9 + h)*t);
        for (int m = tid; m < tile + 8; m += bd) {
            int j = lo - 5 + m;
            int jr = j < 0 ? -j : (j >= half ? 2*half - 2 - j : j);
            jr = jr < 0 ? 0 : (jr > half-1 ? half-1 : jr);
            float2 v = r2[jr];
            ev[ci*st + m] = v.x * sc;
            od[ci*st + m] = v.y * sc;
        }
    }
    __syncthreads();
    const float au = aU[level], ap = aP[level];
    const int c_lo = (lo == 0) ? 0 : lo - 1;
    const int c_hi = (hi == half) ? half : hi + 1;
    float* grb = cout + (((size_t)b*16)*9 + h) * half;

    // ---- phase 1: c = even + tanh(branchU(odd)) over [c_lo, c_hi) ----
    for (int icx = tid; icx < tile/2 + 2; icx += bd) {
        int jb = lo - 2 + icx*2;
        int m0 = icx*2 + 3;
        float acc[16][2];
        #pragma unroll
        for (int c = 0; c < 16; c++) { acc[c][0]=0.f; acc[c][1]=0.f; }
        #pragma unroll
        for (int ci = 0; ci < 16; ci++) {
            const float* orow = od + ci*st + (m0 - 1);
            float2 va = *(const float2*)orow;        // v0 v1
            float2 vb = *(const float2*)(orow + 2);  // v2 v3
            float w0a = va.x, w0b = va.y;            // k=0 window
            float w1a = va.y, w1b = vb.x;            // k=1
            float w2a = vb.x, w2b = vb.y;            // k=2
            const float* w = wu1 + ci*48;
            #pragma unroll
            for (int q = 0; q < 4; q++) {
                float4 wk0 = ((const float4*)(w))[q];
                float4 wk1 = ((const float4*)(w + 16))[q];
                float4 wk2 = ((const float4*)(w + 32))[q];
                acc[q*4+0][0]=fmaf(wk0.x,w0a,fmaf(wk1.x,w1a,fmaf(wk2.x,w2a,acc[q*4+0][0])));
                acc[q*4+0][1]=fmaf(wk0.x,w0b,fmaf(wk1.x,w1b,fmaf(wk2.x,w2b,acc[q*4+0][1])));
                acc[q*4+1][0]=fmaf(wk0.y,w0a,fmaf(wk1.y,w1a,fmaf(wk2.y,w2a,acc[q*4+1][0])));
                acc[q*4+1][1]=fmaf(wk0.y,w0b,fmaf(wk1.y,w1b,fmaf(wk2.y,w2b,acc[q*4+1][1])));
                acc[q*4+2][0]=fmaf(wk0.z,w0a,fmaf(wk1.z,w1a,fmaf(wk2.z,w2a,acc[q*4+2][0])));
                acc[q*4+2][1]=fmaf(wk0.z,w0b,fmaf(wk1.z,w1b,fmaf(wk2.z,w2b,acc[q*4+2][1])));
                acc[q*4+3][0]=fmaf(wk0.w,w0a,fmaf(wk1.w,w1a,fmaf(wk2.w,w2a,acc[q*4+3][0])));
                acc[q*4+3][1]=fmaf(wk0.w,w0b,fmaf(wk1.w,w1b,fmaf(wk2.w,w2b,acc[q*4+3][1])));
            }
        }
        #pragma unroll
        for (int co = 0; co < 16; co++) { acc[co][0] = prelu_f(acc[co][0], au); acc[co][1] = prelu_f(acc[co][1], au); }
        bool full = (jb >= lo) && (jb + 2 <= hi);
        #pragma unroll
        for (int co = 0; co < 16; co++) {
            float s0 = 0.f, s1 = 0.f;
            const float4* w4p = (const float4*)(wu2 + co*16);
            #pragma unroll
            for (int q = 0; q < 4; q++) {
                float4 w = w4p[q];
                s0=fmaf(w.x,acc[4*q][0],fmaf(w.y,acc[4*q+1][0],fmaf(w.z,acc[4*q+2][0],fmaf(w.w,acc[4*q+3][0],s0))));
                s1=fmaf(w.x,acc[4*q][1],fmaf(w.y,acc[4*q+1][1],fmaf(w.z,acc[4*q+2][1],fmaf(w.w,acc[4*q+3][1],s1))));
            }
            float* erow = ev + co*st + m0;
            float c0 = erow[0] + tanh_acc(s0);
            float c1 = erow[1] + tanh_acc(s1);
            if (full) {
                erow[0] = c0; erow[1] = c1;
                float2 r; r.x = c0; r.y = c1;
                *(float2*)(grb + (size_t)co*9*half + jb) = r;
            } else {
                if (jb   >= c_lo && jb   < c_hi) { erow[0] = c0; if (jb   >= lo && jb   < hi) grb[(size_t)co*9*half + jb]   = c0; }
                if (jb+1 >= c_lo && jb+1 < c_hi) { erow[1] = c1; if (jb+1 >= lo && jb+1 < hi) grb[(size_t)co*9*half + jb+1] = c1; }
            }
        }
    }
    __syncthreads();
    if (tid < 16) {              // reflect fixups on c at global edges
        if (lo == 0)    ev[tid*st + 4]        = ev[tid*st + 6];
        if (hi == half) ev[tid*st + tile + 5] = ev[tid*st + tile + 3];
    }
    __syncthreads();

    // ---- phase 2: d = odd - tanh(branchP(c)) over [lo, hi) ----
    for (int id = tid; id < (tile >> 1); id += bd) {
        int m0 = id*2 + 5;
        float acc[16][2];
        #pragma unroll
        for (int c = 0; c < 16; c++) { acc[c][0]=0.f; acc[c][1]=0.f; }
        #pragma unroll
        for (int ci = 0; ci < 16; ci++) {
            const float* erow = ev + ci*st + (m0 - 1);
            float2 va = *(const float2*)erow;
            float2 vb = *(const float2*)(erow + 2);
            float w0a = va.x, w0b = va.y;
            float w1a = va.y, w1b = vb.x;
            float w2a = vb.x, w2b = vb.y;
            const float* w = wp1 + ci*48;
            #pragma unroll
            for (int q = 0; q < 4; q++) {
                float4 wk0 = ((const float4*)(w))[q];
                float4 wk1 = ((const float4*)(w + 16))[q];
                float4 wk2 = ((const float4*)(w + 32))[q];
                acc[q*4+0][0]=fmaf(wk0.x,w0a,fmaf(wk1.x,w1a,fmaf(wk2.x,w2a,acc[q*4+0][0])));
                acc[q*4+0][1]=fmaf(wk0.x,w0b,fmaf(wk1.x,w1b,fmaf(wk2.x,w2b,acc[q*4+0][1])));
                acc[q*4+1][0]=fmaf(wk0.y,w0a,fmaf(wk1.y,w1a,fmaf(wk2.y,w2a,acc[q*4+1][0])));
                acc[q*4+1][1]=fmaf(wk0.y,w0b,fmaf(wk1.y,w1b,fmaf(wk2.y,w2b,acc[q*4+1][1])));
                acc[q*4+2][0]=fmaf(wk0.z,w0a,fmaf(wk1.z,w1a,fmaf(wk2.z,w2a,acc[q*4+2][0])));
                acc[q*4+2][1]=fmaf(wk0.z,w0b,fmaf(wk1.z,w1b,fmaf(wk2.z,w2b,acc[q*4+2][1])));
                acc[q*4+3][0]=fmaf(wk0.w,w0a,fmaf(wk1.w,w1a,fmaf(wk2.w,w2a,acc[q*4+3][0])));
                acc[q*4+3][1]=fmaf(wk0.w,w0b,fmaf(wk1.w,w1b,fmaf(wk2.w,w2b,acc[q*4+3][1])));
            }
        }
        #pragma unroll
        for (int co = 0; co < 16; co++) { acc[co][0] = prelu_f(acc[co][0], ap); acc[co][1] = prelu_f(acc[co][1], ap); }
        #pragma unroll
        for (int co = 0; co < 16; co++) {
            float s0 = 0.f, s1 = 0.f;
            const float4* w4p = (const float4*)(wp2 + co*16);
            #pragma unroll
            for (int q = 0; q < 4; q++) {
                float4 w = w4p[q];
                s0=fmaf(w.x,acc[4*q][0],fmaf(w.y,acc[4*q+1][0],fmaf(w.z,acc[4*q+2][0],fmaf(w.w,acc[4*q+3][0],s0))));
                s1=fmaf(w.x,acc[4*q][1],fmaf(w.y,acc[4*q+1][1],fmaf(w.z,acc[4*q+2][1],fmaf(w.w,acc[4*q+3][1],s1))));
            }
            float* drow = od + co*st + m0;
            drow[0] = drow[0] - tanh_acc(s0);
            drow[1] = drow[1] - tanh_acc(s1);
        }
    }
    __syncthreads();

    // ---- row sums of c (ev) and d (od) over [lo, hi) ----
    const int warp = tid >> 5, lane = tid & 31, nw = bd >> 5;
    for (int ch = warp; ch < 16; ch += nw) {
        float s1 = 0.f, s2 = 0.f;
        for (int m = 5 + lane; m < tile + 5; m += 32) { s1 += ev[ch*st + m]; s2 += od[ch*st + m]; }
        #pragma unroll
        for (int o = 16; o > 0; o >>= 1) {
            s1 += __shfl_xor_sync(0xffffffffu, s1, o);
            s2 += __shfl_xor_sync(0xffffffffu, s2, o);
        }
        if (lane == 0) {
            g_rowsum[(ti*BB + b)*288 + ch*9 + h]       = s1;
            g_rowsum[(ti*BB + b)*288 + 144 + ch*9 + h] = s2;
        }
    }
}

// ================ gate + feats + next-level scale (levels 0..3) =============
__global__ void gate_kernel(const float* __restrict__ gumbel,
                            const float* __restrict__ Wg1, const float* __restrict__ ag1,
                            const float* __restrict__ Wg2, const float* __restrict__ ag2,
                            float* __restrict__ out, int half, int level, int ntiles)
{
    __shared__ float rs[288];
    __shared__ float pl[32];
    __shared__ float mm[4];
    const int b = blockIdx.x, tid = threadIdx.x;
    float v = g_rowsum[b*288 + tid];
    if (ntiles > 1) v += g_rowsum[BB*288 + b*288 + tid];
    rs[tid] = v;
    __syncthreads();
    if (tid < 32) {
        float s = 0.f;
        #pragma unroll
        for (int h = 0; h < 9; h++) s += rs[tid*9 + h];
        pl[tid] = s / (9.f * (float)half);
    }
    __syncthreads();
    if (tid < 2) {
        const int br = tid;
        const float a1 = ag1[level], a2 = ag2[level];
        float hm1[16];
        #pragma unroll
        for (int co = 0; co < 16; co++) {
            float s = 0.f;
            #pragma unroll
            for (int ci = 0; ci < 16; ci++)
                s = fmaf(Wg1[(level*16 + co)*16 + ci], pl[br*16 + ci], s);
            hm1[co] = prelu_f(s, a1);
        }
        float h0 = 0.f, h1 = 0.f;
        #pragma unroll
        for (int ci = 0; ci < 16; ci++) {
            h0 = fmaf(Wg2[(level*2 + 0)*16 + ci], hm1[ci], h0);
            h1 = fmaf(Wg2[(level*2 + 1)*16 + ci], hm1[ci], h1);
        }
        h0 = prelu_f(h0, a2); h1 = prelu_f(h1, a2);
        float mx = fmaxf(h0, h1);
        float e0 = expf(h0 - mx), e1 = expf(h1 - mx);
        float inv = 1.f/(e0 + e1);
        float s0 = e0*inv, s1 = e1*inv;
        const float* g = gumbel + (size_t)(level*256 + b*2 + br)*2;
        float t0 = s0 + g[0], t1 = s1 + g[1];
        mx = fmaxf(t0, t1);
        e0 = expf(t0 - mx); e1 = expf(t1 - mx);
        inv = 1.f/(e0 + e1);
        mm[br*2+0] = e0*inv;
        mm[br*2+1] = e1*inv;
    }
    __syncthreads();
    {
        float m_res = mm[(tid/144)*2 + 1];
        out[(size_t)(b*288 + tid)*9 + level] = m_res * rs[tid] / (float)half;
    }
    if (tid == 0) g_scale[b] = mm[0];
}

// ===== fused deep levels 4..8 (one CTA per batch, 512 threads, gates in-CTA) =
__global__ __launch_bounds__(512) void deep_kernel(
    const float* __restrict__ WU1, const float* __restrict__ WU2, const float* __restrict__ aU,
    const float* __restrict__ WP1, const float* __restrict__ WP2, const float* __restrict__ aP,
    const float* __restrict__ Wg1, const float* __restrict__ ag1,
    const float* __restrict__ Wg2, const float* __restrict__ ag2,
    const float* __restrict__ gumbel, float* __restrict__ out)
{
    extern __shared__ float sm[];
    float* evA = sm;                 // 16*9*64
    float* odA = evA + 9216;
    float* evB = odA + 9216;         // 16*9*32
    float* odB = evB + 4608;
    float* wu1 = odB + 4608;         // 768  [ci][k][co]
    float* wp1 = wu1 + 768;
    float* wu2 = wp1 + 768;          // 256  [co][ci]
    float* wp2 = wu2 + 256;
    float* rs  = wp2 + 256;          // 288
    float* pl  = rs + 288;           // 32
    float* mm  = pl + 32;            // 4
    float* scn = mm + 4;             // 1

    const int b = blockIdx.x, tid = threadIdx.x;
    if (tid == 0) scn[0] = g_scale[b];
    __syncthreads();

    for (int L = 4; L < 9; L++) {
        const int half = 64 >> (L - 4);
        float* ev = ((L - 4) & 1) ? evB : evA;
        float* od = ((L - 4) & 1) ? odB : odA;

        for (int i = tid; i < 768; i += 512) {
            int co = i & 15, k = (i >> 4) % 3, ci = i / 48;
            int gi = ((L*16 + co)*16 + ci)*3 + k;
            wu1[i] = WU1[gi]; wp1[i] = WP1[gi];
        }
        if (tid < 256) { wu2[tid] = WU2[L*256 + tid]; wp2[tid] = WP2[L*256 + tid]; }
        const float sc = scn[0];

        if (L == 4) {
            for (int i = tid; i < 16*9*64; i += 512) {
                int j = i & 63; int r = i >> 6; int h = r % 9; int ci = r / 9;
                const float2* src = (const float2*)(g_buf0 + (((size_t)b*16 + ci)*9 + h)*128);
                float2 v = src[j];
                ev[(ci*9 + h)*64 + j] = v.x * sc;
                od[(ci*9 + h)*64 + j] = v.y * sc;
            }
        } else {
            float* pev = ((L - 5) & 1) ? evB : evA;
            int ph = half * 2;
            for (int i = tid; i < 16*9*half; i += 512) {
                int j = i % half; int r = i / half; int h = r % 9; int ci = r / 9;
                float c0 = pev[(ci*9 + h)*ph + 2*j];
                float c1 = pev[(ci*9 + h)*ph + 2*j + 1];
                ev[(ci*9 + h)*half + j] = c0 * sc;
                od[(ci*9 + h)*half + j] = c1 * sc;
            }
        }
        __syncthreads();
        const float au = aU[L], ap = aP[L];

        // phase 1: c = ev + tanh(U(od))   (float4 weight broadcasts)
        for (int it = tid; it < 9*half; it += 512) {
            int j = it % half, h = it / half;
            int jm = (j == 0) ? 1 : j - 1;
            int jp = (j == half - 1) ? half - 2 : j + 1;
            float acc[16];
            #pragma unroll
            for (int co = 0; co < 16; co++) acc[co] = 0.f;
            #pragma unroll 4
            for (int ci = 0; ci < 16; ci++) {
                const float* orow = od + (ci*9 + h)*half;
                float v0 = orow[jm], v1 = orow[j], v2 = orow[jp];
                const float* w = wu1 + ci*48;
                #pragma unroll
                for (int q = 0; q < 4; q++) {
                    float4 wk0 = ((const float4*)(w))[q];
                    float4 wk1 = ((const float4*)(w + 16))[q];
                    float4 wk2 = ((const float4*)(w + 32))[q];
                    acc[q*4+0]=fmaf(wk0.x,v0,fmaf(wk1.x,v1,fmaf(wk2.x,v2,acc[q*4+0])));
                    acc[q*4+1]=fmaf(wk0.y,v0,fmaf(wk1.y,v1,fmaf(wk2.y,v2,acc[q*4+1])));
                    acc[q*4+2]=fmaf(wk0.z,v0,fmaf(wk1.z,v1,fmaf(wk2.z,v2,acc[q*4+2])));
                    acc[q*4+3]=fmaf(wk0.w,v0,fmaf(wk1.w,v1,fmaf(wk2.w,v2,acc[q*4+3])));
                }
            }
            #pragma unroll
            for (int co = 0; co < 16; co++) acc[co] = prelu_f(acc[co], au);
            #pragma unroll
            for (int co = 0; co < 16; co++) {
                float s = 0.f;
                const float4* w4p = (const float4*)(wu2 + co*16);
                #pragma unroll
                for (int q = 0; q < 4; q++) {
                    float4 w = w4p[q];
                    s=fmaf(w.x,acc[4*q],fmaf(w.y,acc[4*q+1],fmaf(w.z,acc[4*q+2],fmaf(w.w,acc[4*q+3],s))));
                }
                ev[(co*9 + h)*half + j] += tanh_acc(s);
            }
        }
        __syncthreads();

        // phase 2: d = od - tanh(P(c))
        for (int it = tid; it < 9*half; it += 512) {
            int j = it % half, h = it / half;
            int jm = (j == 0) ? 1 : j - 1;
            int jp = (j == half - 1) ? half - 2 : j + 1;
            float acc[16];
            #pragma unroll
            for (int co = 0; co < 16; co++) acc[co] = 0.f;
            #pragma unroll 4
            for (int ci = 0; ci < 16; ci++) {
                const float* erow = ev + (ci*9 + h)*half;
                float v0 = erow[jm], v1 = erow[j], v2 = erow[jp];
                const float* w = wp1 + ci*48;
                #pragma unroll
                for (int q = 0; q < 4; q++) {
                    float4 wk0 = ((const float4*)(w))[q];
                    float4 wk1 = ((const float4*)(w + 16))[q];
                    float4 wk2 = ((const float4*)(w + 32))[q];
                    acc[q*4+0]=fmaf(wk0.x,v0,fmaf(wk1.x,v1,fmaf(wk2.x,v2,acc[q*4+0])));
                    acc[q*4+1]=fmaf(wk0.y,v0,fmaf(wk1.y,v1,fmaf(wk2.y,v2,acc[q*4+1])));
                    acc[q*4+2]=fmaf(wk0.z,v0,fmaf(wk1.z,v1,fmaf(wk2.z,v2,acc[q*4+2])));
                    acc[q*4+3]=fmaf(wk0.w,v0,fmaf(wk1.w,v1,fmaf(wk2.w,v2,acc[q*4+3])));
                }
            }
            #pragma unroll
            for (int co = 0; co < 16; co++) acc[co] = prelu_f(acc[co], ap);
            #pragma unroll
            for (int co = 0; co < 16; co++) {
                float s = 0.f;
                const float4* w4p = (const float4*)(wp2 + co*16);
                #pragma unroll
                for (int q = 0; q < 4; q++) {
                    float4 w = w4p[q];
                    s=fmaf(w.x,acc[4*q],fmaf(w.y,acc[4*q+1],fmaf(w.z,acc[4*q+2],fmaf(w.w,acc[4*q+3],s))));
                }
                od[(co*9 + h)*half + j] -= tanh_acc(s);
            }
        }
        __syncthreads();

        // row sums
        if (tid < 144) {
            int ch = tid / 9, h = tid % 9;
            float s1 = 0.f, s2 = 0.f;
            const float* er = ev + (ch*9 + h)*half;
            const float* dr = od + (ch*9 + h)*half;
            for (int j = 0; j < half; j++) { s1 += er[j]; s2 += dr[j]; }
            rs[ch*9 + h] = s1; rs[144 + ch*9 + h] = s2;
        }
        __syncthreads();
        if (tid < 32) {
            float s = 0.f;
            #pragma unroll
            for (int h = 0; h < 9; h++) s += rs[tid*9 + h];
            pl[tid] = s / (9.f * (float)half);
        }
        __syncthreads();
        if (tid < 2) {
            const int br = tid;
            const float a1 = ag1[L], a2 = ag2[L];
            float hm1[16];
            #pragma unroll
            for (int co = 0; co < 16; co++) {
                float s = 0.f;
                #pragma unroll
                for (int ci = 0; ci < 16; ci++)
                    s = fmaf(Wg1[(L*16 + co)*16 + ci], pl[br*16 + ci], s);
                hm1[co] = prelu_f(s, a1);
            }
            float h0 = 0.f, h1 = 0.f;
            #pragma unroll
            for (int ci = 0; ci < 16; ci++) {
                h0 = fmaf(Wg2[(L*2 + 0)*16 + ci], hm1[ci], h0);
                h1 = fmaf(Wg2[(L*2 + 1)*16 + ci], hm1[ci], h1);
            }
            h0 = prelu_f(h0, a2); h1 = prelu_f(h1, a2);
            float mx = fmaxf(h0, h1);
            float e0 = expf(h0 - mx), e1 = expf(h1 - mx);
            float inv = 1.f/(e0 + e1);
            float s0 = e0*inv, s1 = e1*inv;
            const float* g = gumbel + (size_t)(L*256 + b*2 + br)*2;
            float t0 = s0 + g[0], t1 = s1 + g[1];
            mx = fmaxf(t0, t1);
            e0 = expf(t0 - mx); e1 = expf(t1 - mx);
            inv = 1.f/(e0 + e1);
            mm[br*2+0] = e0*inv;
            mm[br*2+1] = e1*inv;
        }
        __syncthreads();
        for (int i = tid; i < 288; i += 512) {
            float m_res = mm[(i/144)*2 + 1];
            out[(size_t)(b*288 + i)*9 + L] = m_res * rs[i] / (float)half;
        }
        if (tid == 0) scn[0] = mm[0];
        __syncthreads();
    }
}

// =================== launch ===================
extern "C" void kernel_launch(void* const* d_in, const int* in_sizes, int n_in,
                              void* d_out, int out_size)
{
    const float* x    = (const float*)d_in[0];
    const float* gum  = (const float*)d_in[1];
    const float* Wc1  = (const float*)d_in[2];
    const float* bc1  = (const float*)d_in[3];
    const float* g1   = (const float*)d_in[4];
    const float* b1   = (const float*)d_in[5];
    const float* a1   = (const float*)d_in[6];
    const float* Wc2  = (const float*)d_in[7];
    const float* bc2  = (const float*)d_in[8];
    const float* g2   = (const float*)d_in[9];
    const float* b2   = (const float*)d_in[10];
    const float* a2   = (const float*)d_in[11];
    const float* WP1  = (const float*)d_in[12];
    const float* aP   = (const float*)d_in[13];
    const float* WP2  = (const float*)d_in[14];
    const float* WU1  = (const float*)d_in[15];
    const float* aU   = (const float*)d_in[16];
    const float* WU2  = (const float*)d_in[17];
    const float* Wg1  = (const float*)d_in[18];
    const float* ag1  = (const float*)d_in[19];
    const float* Wg2  = (const float*)d_in[20];
    const float* ag2  = (const float*)d_in[21];
    float* out = (float*)d_out;

    const int front_smem = (2000 + 16*520) * 4;                // 41280 B -> 5 CTAs/SM
    const int lift_smem_max = (2048 + 32*(512 + 8)) * 4;       // 74752 B
    const int deep_smem = (9216*2 + 4608*2 + 768*2 + 256*2 + 288 + 32 + 4 + 4) * 4;
    cudaFuncSetAttribute(front_kernel, cudaFuncAttributeMaxDynamicSharedMemorySize, front_smem);
    cudaFuncSetAttribute(lift_kernel,  cudaFuncAttributeMaxDynamicSharedMemorySize, lift_smem_max);
    cudaFuncSetAttribute(deep_kernel,  cudaFuncAttributeMaxDynamicSharedMemorySize, deep_smem);

    front_kernel<<<BB*HH*4, 256, front_smem>>>(x, Wc1, bc1, g1, b1, a1, Wc2, bc2, g2, b2, a2);

    int t = TT;
    for (int lvl = 0; lvl < 4; lvl++) {
        const int half = t >> 1;
        const int ntiles = (lvl <= 1) ? 2 : 1;     // L0 tile 512, L1 tile 256
        const int tile = half / ntiles;
        const int chunks = tile/2 + 2;
        int blk = ((chunks + 31) / 32) * 32;
        if (blk > 256) blk = 256;
        if (blk < 64) blk = 64;
        const int smem = (2048 + 32*(tile + 8)) * 4;
        lift_kernel<<<BB*HH*ntiles, blk, smem>>>(WU1, WU2, aU, WP1, WP2, aP, t, lvl, ntiles);
        gate_kernel<<<BB, 288>>>(gum, Wg1, ag1, Wg2, ag2, out, half, lvl, ntiles);
        t = half;
    }

    deep_kernel<<<BB, 512, deep_smem>>>(WU1, WU2, aU, WP1, WP2, aP,
                                        Wg1, ag1, Wg2, ag2, gum, out);
}